// round 1
// baseline (speedup 1.0000x reference)
#include <cuda_runtime.h>
#include <math.h>

#define Bb 4
#define Nn 10000
#define Dd 128
#define DE 32
#define Ee 640000
#define NODES (Bb*Nn)          // 40000
#define RSQRT_DH 0.17677669529663687f  // 1/sqrt(32)

// ---------------- scratch (device globals; no allocation allowed) ------------
__device__ float g_V[NODES * Dd];       // 20.5 MB
__device__ float g_qa[NODES];
__device__ float g_ka[NODES];
__device__ float g_att_sum[NODES];
__device__ float g_att_exp[Ee];
__device__ int   g_counts[NODES];
__device__ int   g_offsets[NODES + 1];
__device__ int   g_cursor[NODES];
__device__ int   g_perm[Ee];
__device__ float g_wqa[Dd];
__device__ float g_wka[Dd];
__device__ float g_wewa[DE];
__device__ float g_cc;                  // (bq+bk+bew)·Wa

// ---------------- K0: fold Wa into the projection weights -------------------
__global__ void k_prep(const float* __restrict__ Wq, const float* __restrict__ Wk,
                       const float* __restrict__ Wew,
                       const float* __restrict__ bq, const float* __restrict__ bk,
                       const float* __restrict__ bew, const float* __restrict__ Wa) {
    int i = threadIdx.x;  // 128 threads
    float a = 0.f, b = 0.f;
    for (int j = 0; j < Dd; j++) {
        float wa = Wa[j];
        a += Wq[i * Dd + j] * wa;
        b += Wk[i * Dd + j] * wa;
    }
    g_wqa[i] = a;
    g_wka[i] = b;
    if (i < DE) {
        float c = 0.f;
        for (int j = 0; j < Dd; j++) c += Wew[i * Dd + j] * Wa[j];
        g_wewa[i] = c;
    }
    if (i == 0) {
        float cc = 0.f;
        for (int j = 0; j < Dd; j++) cc += (bq[j] + bk[j] + bew[j]) * Wa[j];
        g_cc = cc;
    }
}

// ---------------- K1: zero accumulators --------------------------------------
__global__ void k_zero() {
    int i = blockIdx.x * blockDim.x + threadIdx.x;
    if (i < NODES) { g_att_sum[i] = 0.f; g_counts[i] = 0; }
}

// ---------------- K2: V = x @ Wv + bv  (fp32 SGEMM, 128x128 tiles) -----------
#define BM 128
#define BN 128
#define BK 16
__global__ void k_gemm_v(const float* __restrict__ x, const float* __restrict__ Wv,
                         const float* __restrict__ bv) {
    __shared__ float xs[BM][BK + 1];
    __shared__ float ws[BK][BN];
    int t  = threadIdx.x;          // 256 threads
    int tx = t & 15, ty = t >> 4;  // 16x16
    int m0 = blockIdx.x * BM;
    float acc[8][8];
    #pragma unroll
    for (int i = 0; i < 8; i++)
        #pragma unroll
        for (int j = 0; j < 8; j++) acc[i][j] = 0.f;

    for (int kk = 0; kk < Dd; kk += BK) {
        // load x tile [BM x BK]  (512 float4s)
        #pragma unroll
        for (int it = 0; it < 2; it++) {
            int lin = t + it * 256;        // quad index
            int m = lin >> 2, kq = lin & 3;
            float4 v = make_float4(0.f, 0.f, 0.f, 0.f);
            if (m0 + m < NODES)
                v = *(const float4*)&x[(size_t)(m0 + m) * Dd + kk + kq * 4];
            xs[m][kq * 4 + 0] = v.x;
            xs[m][kq * 4 + 1] = v.y;
            xs[m][kq * 4 + 2] = v.z;
            xs[m][kq * 4 + 3] = v.w;
        }
        // load W tile [BK x BN]
        #pragma unroll
        for (int it = 0; it < 2; it++) {
            int q = t + it * 256;
            int k = q >> 5, c4 = q & 31;
            float4 w = *(const float4*)&Wv[(size_t)(kk + k) * Dd + c4 * 4];
            *(float4*)&ws[k][c4 * 4] = w;
        }
        __syncthreads();
        #pragma unroll
        for (int k = 0; k < BK; k++) {
            float xv[8], wv[8];
            #pragma unroll
            for (int i = 0; i < 8; i++) xv[i] = xs[ty * 8 + i][k];
            #pragma unroll
            for (int j = 0; j < 8; j++) wv[j] = ws[k][tx * 8 + j];
            #pragma unroll
            for (int i = 0; i < 8; i++)
                #pragma unroll
                for (int j = 0; j < 8; j++) acc[i][j] += xv[i] * wv[j];
        }
        __syncthreads();
    }
    #pragma unroll
    for (int i = 0; i < 8; i++) {
        int r = m0 + ty * 8 + i;
        if (r < NODES) {
            #pragma unroll
            for (int j = 0; j < 8; j++) {
                int c = tx * 8 + j;
                g_V[(size_t)r * Dd + c] = acc[i][j] + bv[c];
            }
        }
    }
}

// ---------------- K3: per-node attention scalars qa, ka ----------------------
__global__ void k_qaka(const float* __restrict__ x) {
    int warp = (blockIdx.x * blockDim.x + threadIdx.x) >> 5;
    int lane = threadIdx.x & 31;
    if (warp >= NODES) return;
    float4 xv = *(const float4*)&x[(size_t)warp * Dd + lane * 4];
    float4 wq = *(const float4*)&g_wqa[lane * 4];
    float4 wk = *(const float4*)&g_wka[lane * 4];
    float a = xv.x * wq.x + xv.y * wq.y + xv.z * wq.z + xv.w * wq.w;
    float b = xv.x * wk.x + xv.y * wk.y + xv.z * wk.z + xv.w * wk.w;
    #pragma unroll
    for (int off = 16; off > 0; off >>= 1) {
        a += __shfl_xor_sync(0xffffffffu, a, off);
        b += __shfl_xor_sync(0xffffffffu, b, off);
    }
    if (lane == 0) { g_qa[warp] = a; g_ka[warp] = b; }
}

// ---------------- K4: edge pass 1 — exp(logit), segment sums, histogram ------
__global__ void k_edge1(const int* __restrict__ ei, const float* __restrict__ e_emb,
                        const int* __restrict__ bi) {
    __shared__ float ws4[DE];
    __shared__ float s_cc;
    if (threadIdx.x < DE) ws4[threadIdx.x] = g_wewa[threadIdx.x];
    if (threadIdx.x == 0) s_cc = g_cc;
    __syncthreads();
    int e = blockIdx.x * blockDim.x + threadIdx.x;
    if (e >= Ee) return;
    int src = ei[e];
    int dst = ei[Ee + e];
    int b   = bi[e];
    const float4* ep = (const float4*)(e_emb + (size_t)e * DE);
    float dot = 0.f;
    #pragma unroll
    for (int i = 0; i < 8; i++) {
        float4 v = ep[i];
        dot += v.x * ws4[i * 4 + 0] + v.y * ws4[i * 4 + 1] +
               v.z * ws4[i * 4 + 2] + v.w * ws4[i * 4 + 3];
    }
    float logit = (g_qa[b * Nn + src] + g_ka[b * Nn + dst] + dot + s_cc) * RSQRT_DH;
    float ex = expf(logit);
    g_att_exp[e] = ex;
    atomicAdd(&g_att_sum[b * Nn + dst], ex);
    atomicAdd(&g_counts[b * Nn + src], 1);
}

// ---------------- K5: single-block exclusive scan of counts ------------------
#define SCAN_T 1024
#define SCAN_CH 40
__global__ void k_scan() {
    __shared__ int sh[SCAN_T];
    int t = threadIdx.x;
    int start = t * SCAN_CH;
    int end = min(start + SCAN_CH, NODES);
    int s = 0;
    for (int i = start; i < end; i++) s += g_counts[i];
    sh[t] = s;
    __syncthreads();
    for (int off = 1; off < SCAN_T; off <<= 1) {
        int v = (t >= off) ? sh[t - off] : 0;
        __syncthreads();
        sh[t] += v;
        __syncthreads();
    }
    int run = (t == 0) ? 0 : sh[t - 1];
    for (int i = start; i < end; i++) {
        g_offsets[i] = run;
        g_cursor[i] = run;
        run += g_counts[i];
    }
    if (t == SCAN_T - 1) g_offsets[NODES] = sh[SCAN_T - 1];
}

// ---------------- K6: scatter edge ids into src-sorted order -----------------
__global__ void k_scatter(const int* __restrict__ ei, const int* __restrict__ bi) {
    int e = blockIdx.x * blockDim.x + threadIdx.x;
    if (e >= Ee) return;
    int key = bi[e] * Nn + ei[e];
    int pos = atomicAdd(&g_cursor[key], 1);
    g_perm[pos] = e;
}

// ---------------- K7: gather+aggregate, one warp per src node ----------------
__global__ void k_gather(const int* __restrict__ ei, const float* __restrict__ e_emb,
                         const float* __restrict__ Wev, const float* __restrict__ bev,
                         float* __restrict__ out) {
    __shared__ float wev_sh[DE * Dd];   // 16 KB
    __shared__ float bev_sh[Dd];
    for (int i = threadIdx.x; i < DE * Dd; i += blockDim.x) wev_sh[i] = Wev[i];
    if (threadIdx.x < Dd) bev_sh[threadIdx.x] = bev[threadIdx.x];
    __syncthreads();

    int s = blockIdx.x * 8 + (threadIdx.x >> 5);
    int lane = threadIdx.x & 31;
    if (s >= NODES) return;

    int start = g_offsets[s];
    int end   = g_offsets[s + 1];
    int base  = (s / Nn) * Nn;

    float4 accv = make_float4(0.f, 0.f, 0.f, 0.f);
    float4 acce = make_float4(0.f, 0.f, 0.f, 0.f);
    float  accA = 0.f;

    for (int i = start; i < end; i++) {
        int e = g_perm[i];
        int dst = ei[Ee + e];
        float ex = g_att_exp[e];
        float alpha = ex / (g_att_sum[base + dst] + 1e-9f);
        const float4* vr = (const float4*)(g_V + (size_t)(base + dst) * Dd);
        float4 v = vr[lane];
        accv.x += alpha * v.x; accv.y += alpha * v.y;
        accv.z += alpha * v.z; accv.w += alpha * v.w;
        if (lane < 8) {
            const float4* er = (const float4*)(e_emb + (size_t)e * DE);
            float4 ev = er[lane];
            acce.x += alpha * ev.x; acce.y += alpha * ev.y;
            acce.z += alpha * ev.z; acce.w += alpha * ev.w;
        }
        accA += alpha;
    }

    int c0 = lane * 4;
    float res[4];
    res[0] = accv.x + accA * bev_sh[c0 + 0];
    res[1] = accv.y + accA * bev_sh[c0 + 1];
    res[2] = accv.z + accA * bev_sh[c0 + 2];
    res[3] = accv.w + accA * bev_sh[c0 + 3];
    float ea[4] = {acce.x, acce.y, acce.z, acce.w};
    #pragma unroll
    for (int i = 0; i < DE; i++) {
        float av = __shfl_sync(0xffffffffu, ea[i & 3], i >> 2);
        const float* wr = &wev_sh[i * Dd + c0];
        res[0] += av * wr[0];
        res[1] += av * wr[1];
        res[2] += av * wr[2];
        res[3] += av * wr[3];
    }
    float4 o = make_float4(res[0], res[1], res[2], res[3]);
    *(float4*)&out[(size_t)s * Dd + c0] = o;
}

// ---------------- launch ------------------------------------------------------
extern "C" void kernel_launch(void* const* d_in, const int* in_sizes, int n_in,
                              void* d_out, int out_size) {
    const float* x     = (const float*)d_in[0];
    const int*   ei    = (const int*)  d_in[1];
    const float* e_emb = (const float*)d_in[2];
    const int*   bi    = (const int*)  d_in[3];
    const float* Wq    = (const float*)d_in[4];
    const float* bq    = (const float*)d_in[5];
    const float* Wk    = (const float*)d_in[6];
    const float* bk    = (const float*)d_in[7];
    const float* Wv    = (const float*)d_in[8];
    const float* bv    = (const float*)d_in[9];
    const float* Wew   = (const float*)d_in[10];
    const float* bew   = (const float*)d_in[11];
    const float* Wev   = (const float*)d_in[12];
    const float* bev   = (const float*)d_in[13];
    const float* Wa    = (const float*)d_in[14];
    float* out = (float*)d_out;

    k_prep<<<1, 128>>>(Wq, Wk, Wew, bq, bk, bew, Wa);
    k_zero<<<(NODES + 255) / 256, 256>>>();
    k_gemm_v<<<(NODES + BM - 1) / BM, 256>>>(x, Wv, bv);
    k_qaka<<<(NODES + 7) / 8, 256>>>(x);
    k_edge1<<<(Ee + 255) / 256, 256>>>(ei, e_emb, bi);
    k_scan<<<1, SCAN_T>>>();
    k_scatter<<<(Ee + 255) / 256, 256>>>(ei, bi);
    k_gather<<<(NODES + 7) / 8, 256>>>(ei, e_emb, Wev, bev, out);
}

// round 4
// speedup vs baseline: 1.1949x; 1.1949x over previous
#include <cuda_runtime.h>
#include <math.h>
#include <stdint.h>

#define Bb 4
#define Nn 10000
#define Dd 128
#define DE 32
#define Ee 640000
#define NODES (Bb*Nn)            // 40000
#define NODES_PAD 40064          // 313 * 128
#define RSQRT_DH 0.17677669529663687f

// ---------------- scratch (device globals; zero-init, no allocation) ---------
__device__ float g_qa[NODES];
__device__ float g_ka[NODES];
__device__ float g_att_sum[NODES];
__device__ float g_att_exp[Ee];
__device__ int   g_counts[NODES];
__device__ int   g_offsets[NODES + 1];
__device__ int   g_cursor[NODES];
__device__ int4  g_edge[Ee];             // {e, dst_node, alpha_bits, 0} sorted by src
__device__ float g_Mx[NODES_PAD * Dd];   // Σ alpha * x[dst]
__device__ float g_Me[NODES_PAD * DE];   // Σ alpha * e_emb[e]
__device__ float g_sA[NODES_PAD];        // Σ alpha
__device__ float g_wqa[Dd];
__device__ float g_wka[Dd];
__device__ float g_wewa[DE];
__device__ float g_bvev[Dd];             // bv + bev
__device__ float g_cc;                   // (bq+bk+bew)·Wa

// ---------------- cp.async helpers ------------------------------------------
__device__ __forceinline__ void cp16(void* dst, const void* src) {
    uint32_t d = (uint32_t)__cvta_generic_to_shared(dst);
    asm volatile("cp.async.cg.shared.global [%0], [%1], 16;" :: "r"(d), "l"(src));
}
#define CP_COMMIT() asm volatile("cp.async.commit_group;")
#define CP_WAIT(n)  asm volatile("cp.async.wait_group %0;" :: "n"(n))

// ---------------- K0: fold Wa into projections; bias combos -----------------
__global__ void k_prep(const float* __restrict__ Wq, const float* __restrict__ Wk,
                       const float* __restrict__ Wew,
                       const float* __restrict__ bq, const float* __restrict__ bk,
                       const float* __restrict__ bew, const float* __restrict__ Wa,
                       const float* __restrict__ bv, const float* __restrict__ bev) {
    int i = threadIdx.x;  // 128 threads
    float a = 0.f, b = 0.f;
    for (int j = 0; j < Dd; j++) {
        float wa = Wa[j];
        a += Wq[i * Dd + j] * wa;
        b += Wk[i * Dd + j] * wa;
    }
    g_wqa[i] = a;
    g_wka[i] = b;
    g_bvev[i] = bv[i] + bev[i];
    if (i < DE) {
        float c = 0.f;
        for (int j = 0; j < Dd; j++) c += Wew[i * Dd + j] * Wa[j];
        g_wewa[i] = c;
    }
    if (i == 0) {
        float cc = 0.f;
        for (int j = 0; j < Dd; j++) cc += (bq[j] + bk[j] + bew[j]) * Wa[j];
        g_cc = cc;
    }
}

// ---------------- K1: zero accumulators --------------------------------------
__global__ void k_zero() {
    int i = blockIdx.x * blockDim.x + threadIdx.x;
    if (i < NODES) { g_att_sum[i] = 0.f; g_counts[i] = 0; }
}

// ---------------- K2: per-node attention scalars qa, ka ----------------------
__global__ void k_qaka(const float* __restrict__ x) {
    int warp = (blockIdx.x * blockDim.x + threadIdx.x) >> 5;
    int lane = threadIdx.x & 31;
    if (warp >= NODES) return;
    float4 xv = *(const float4*)&x[(size_t)warp * Dd + lane * 4];
    float4 wq = *(const float4*)&g_wqa[lane * 4];
    float4 wk = *(const float4*)&g_wka[lane * 4];
    float a = xv.x * wq.x + xv.y * wq.y + xv.z * wq.z + xv.w * wq.w;
    float b = xv.x * wk.x + xv.y * wk.y + xv.z * wk.z + xv.w * wk.w;
    #pragma unroll
    for (int off = 16; off > 0; off >>= 1) {
        a += __shfl_xor_sync(0xffffffffu, a, off);
        b += __shfl_xor_sync(0xffffffffu, b, off);
    }
    if (lane == 0) { g_qa[warp] = a; g_ka[warp] = b; }
}

// ---------------- K3: edge pass — exp(logit), segment sums, histogram --------
__global__ void k_edge1(const int* __restrict__ ei, const float* __restrict__ e_emb,
                        const int* __restrict__ bi) {
    __shared__ float ws4[DE];
    __shared__ float s_cc;
    if (threadIdx.x < DE) ws4[threadIdx.x] = g_wewa[threadIdx.x];
    if (threadIdx.x == 0) s_cc = g_cc;
    __syncthreads();
    int e = blockIdx.x * blockDim.x + threadIdx.x;
    if (e >= Ee) return;
    int src = ei[e];
    int dst = ei[Ee + e];
    int b   = bi[e];
    const float4* ep = (const float4*)(e_emb + (size_t)e * DE);
    float dot = 0.f;
    #pragma unroll
    for (int i = 0; i < 8; i++) {
        float4 v = ep[i];
        dot += v.x * ws4[i * 4 + 0] + v.y * ws4[i * 4 + 1] +
               v.z * ws4[i * 4 + 2] + v.w * ws4[i * 4 + 3];
    }
    float logit = (g_qa[b * Nn + src] + g_ka[b * Nn + dst] + dot + s_cc) * RSQRT_DH;
    float ex = expf(logit);
    g_att_exp[e] = ex;
    atomicAdd(&g_att_sum[b * Nn + dst], ex);
    atomicAdd(&g_counts[b * Nn + src], 1);
}

// ---------------- K4: single-block exclusive scan of counts ------------------
#define SCAN_T 1024
#define SCAN_CH 40
__global__ void k_scan() {
    __shared__ int sh[SCAN_T];
    int t = threadIdx.x;
    int start = t * SCAN_CH;
    int end = min(start + SCAN_CH, NODES);
    int s = 0;
    for (int i = start; i < end; i++) s += g_counts[i];
    sh[t] = s;
    __syncthreads();
    for (int off = 1; off < SCAN_T; off <<= 1) {
        int v = (t >= off) ? sh[t - off] : 0;
        __syncthreads();
        sh[t] += v;
        __syncthreads();
    }
    int run = (t == 0) ? 0 : sh[t - 1];
    for (int i = start; i < end; i++) {
        g_offsets[i] = run;
        g_cursor[i] = run;
        run += g_counts[i];
    }
    if (t == SCAN_T - 1) g_offsets[NODES] = sh[SCAN_T - 1];
}

// ---------------- K5: scatter packed {e, dst, alpha} into src order ----------
__global__ void k_scatter(const int* __restrict__ ei, const int* __restrict__ bi) {
    int e = blockIdx.x * blockDim.x + threadIdx.x;
    if (e >= Ee) return;
    int b = bi[e];
    int key  = b * Nn + ei[e];        // source node (sort key)
    int dstn = b * Nn + ei[Ee + e];   // destination node
    float alpha = g_att_exp[e] / (g_att_sum[dstn] + 1e-9f);
    int pos = atomicAdd(&g_cursor[key], 1);
    int4 pk;
    pk.x = e;
    pk.y = dstn;
    pk.z = __float_as_int(alpha);
    pk.w = 0;
    g_edge[pos] = pk;
}

// ---------------- K6: gather moments, one warp per src node ------------------
// Software-pipelined: prefetch next edge record while consuming current one so
// the random x-row load address is always ready (breaks the 2-deep chain).
__global__ void k_gather(const float* __restrict__ x, const float* __restrict__ e_emb) {
    int s = blockIdx.x * 8 + (threadIdx.x >> 5);
    int lane = threadIdx.x & 31;
    if (s >= NODES) return;

    int start = g_offsets[s];
    int end   = g_offsets[s + 1];

    float4 accx = make_float4(0.f, 0.f, 0.f, 0.f);
    float4 acce = make_float4(0.f, 0.f, 0.f, 0.f);
    float  accA = 0.f;

    if (start < end) {
        int4 m = g_edge[start];
        for (int i = start; i < end; i++) {
            int4 nextm;
            if (i + 1 < end) nextm = g_edge[i + 1];
            float a = __int_as_float(m.z);
            float4 v = *(const float4*)&x[(size_t)m.y * Dd + lane * 4];
            float4 ev = make_float4(0.f, 0.f, 0.f, 0.f);
            if (lane < 8) ev = *(const float4*)&e_emb[(size_t)m.x * DE + lane * 4];
            accx.x += a * v.x; accx.y += a * v.y;
            accx.z += a * v.z; accx.w += a * v.w;
            acce.x += a * ev.x; acce.y += a * ev.y;
            acce.z += a * ev.z; acce.w += a * ev.w;
            accA += a;
            m = nextm;
        }
    }

    *(float4*)&g_Mx[(size_t)s * Dd + lane * 4] = accx;
    if (lane < 8) *(float4*)&g_Me[(size_t)s * DE + lane * 4] = acce;
    if (lane == 0) g_sA[s] = accA;
}

// ---------------- K7: fused epilogue GEMM  out = [Mx|Me]@[Wv;Wev] + sA⊗(bv+bev)
#define OB_M 128
#define OB_K 16
#define NTILES 10   // 8 tiles from Mx/Wv (K=128) + 2 tiles from Me/Wev (K=32)
__global__ __launch_bounds__(256) void k_out(const float* __restrict__ Wv,
                                             const float* __restrict__ Wev,
                                             float* __restrict__ out) {
    __shared__ float As[2][OB_M * OB_K];   // row-major [m][k]
    __shared__ float Bs[2][OB_K * Dd];     // [k][n]
    __shared__ float sA_sh[OB_M];
    __shared__ float bb_sh[Dd];

    int t  = threadIdx.x;
    int m0 = blockIdx.x * OB_M;
    if (t < OB_M) {
        sA_sh[t] = g_sA[m0 + t];   // padded array, rows >= NODES are zero
        bb_sh[t] = g_bvev[t];
    }

    auto issue = [&](int stage, int tile) {
        #pragma unroll
        for (int it = 0; it < 2; it++) {
            int q = t + it * 256;
            // A chunk: m = q>>2, kq = q&3
            int m = q >> 2, kq = q & 3;
            const float* srcA = (tile < 8)
                ? &g_Mx[(size_t)(m0 + m) * Dd + tile * OB_K + kq * 4]
                : &g_Me[(size_t)(m0 + m) * DE + (tile - 8) * OB_K + kq * 4];
            cp16(&As[stage][m * OB_K + kq * 4], srcA);
            // B chunk: k = q>>5, c4 = q&31
            int k = q >> 5, c4 = q & 31;
            const float* srcB = (tile < 8)
                ? &Wv[(size_t)(tile * OB_K + k) * Dd + c4 * 4]
                : &Wev[(size_t)((tile - 8) * OB_K + k) * Dd + c4 * 4];
            cp16(&Bs[stage][k * Dd + c4 * 4], srcB);
        }
    };

    issue(0, 0);
    CP_COMMIT();

    float acc[8][8];
    #pragma unroll
    for (int i = 0; i < 8; i++)
        #pragma unroll
        for (int j = 0; j < 8; j++) acc[i][j] = 0.f;

    int tx = t & 15, ty = t >> 4;

    for (int tile = 0; tile < NTILES; tile++) {
        int cur = tile & 1, nxt = cur ^ 1;
        if (tile + 1 < NTILES) {
            issue(nxt, tile + 1);
            CP_COMMIT();
            CP_WAIT(1);
        } else {
            CP_WAIT(0);
        }
        __syncthreads();
        #pragma unroll
        for (int k = 0; k < OB_K; k++) {
            float xv[8];
            #pragma unroll
            for (int i = 0; i < 8; i++) xv[i] = As[cur][(ty * 8 + i) * OB_K + k];
            float4 w0 = *(float4*)&Bs[cur][k * Dd + tx * 8];
            float4 w1 = *(float4*)&Bs[cur][k * Dd + tx * 8 + 4];
            #pragma unroll
            for (int i = 0; i < 8; i++) {
                acc[i][0] += xv[i] * w0.x;
                acc[i][1] += xv[i] * w0.y;
                acc[i][2] += xv[i] * w0.z;
                acc[i][3] += xv[i] * w0.w;
                acc[i][4] += xv[i] * w1.x;
                acc[i][5] += xv[i] * w1.y;
                acc[i][6] += xv[i] * w1.z;
                acc[i][7] += xv[i] * w1.w;
            }
        }
        __syncthreads();
    }

    #pragma unroll
    for (int i = 0; i < 8; i++) {
        int r = m0 + ty * 8 + i;
        if (r < NODES) {
            float sa = sA_sh[ty * 8 + i];
            int c0 = tx * 8;
            float4 o0, o1;
            o0.x = acc[i][0] + sa * bb_sh[c0 + 0];
            o0.y = acc[i][1] + sa * bb_sh[c0 + 1];
            o0.z = acc[i][2] + sa * bb_sh[c0 + 2];
            o0.w = acc[i][3] + sa * bb_sh[c0 + 3];
            o1.x = acc[i][4] + sa * bb_sh[c0 + 4];
            o1.y = acc[i][5] + sa * bb_sh[c0 + 5];
            o1.z = acc[i][6] + sa * bb_sh[c0 + 6];
            o1.w = acc[i][7] + sa * bb_sh[c0 + 7];
            *(float4*)&out[(size_t)r * Dd + c0]     = o0;
            *(float4*)&out[(size_t)r * Dd + c0 + 4] = o1;
        }
    }
}

// ---------------- launch ------------------------------------------------------
extern "C" void kernel_launch(void* const* d_in, const int* in_sizes, int n_in,
                              void* d_out, int out_size) {
    const float* x     = (const float*)d_in[0];
    const int*   ei    = (const int*)  d_in[1];
    const float* e_emb = (const float*)d_in[2];
    const int*   bi    = (const int*)  d_in[3];
    const float* Wq    = (const float*)d_in[4];
    const float* bq    = (const float*)d_in[5];
    const float* Wk    = (const float*)d_in[6];
    const float* bk    = (const float*)d_in[7];
    const float* Wv    = (const float*)d_in[8];
    const float* bv    = (const float*)d_in[9];
    const float* Wew   = (const float*)d_in[10];
    const float* bew   = (const float*)d_in[11];
    const float* Wev   = (const float*)d_in[12];
    const float* bev   = (const float*)d_in[13];
    const float* Wa    = (const float*)d_in[14];
    float* out = (float*)d_out;

    k_prep<<<1, 128>>>(Wq, Wk, Wew, bq, bk, bew, Wa, bv, bev);
    k_zero<<<(NODES + 255) / 256, 256>>>();
    k_qaka<<<(NODES + 7) / 8, 256>>>(x);
    k_edge1<<<(Ee + 255) / 256, 256>>>(ei, e_emb, bi);
    k_scan<<<1, SCAN_T>>>();
    k_scatter<<<(Ee + 255) / 256, 256>>>(ei, bi);
    k_gather<<<(NODES + 7) / 8, 256>>>(x, e_emb);
    k_out<<<NODES_PAD / OB_M, 256>>>(Wv, Wev, out);
}

// round 6
// speedup vs baseline: 1.2757x; 1.0677x over previous
#include <cuda_runtime.h>
#include <math.h>
#include <stdint.h>

#define Bb 4
#define Nn 10000
#define Dd 128
#define DE 32
#define Ee 640000
#define NODES (Bb*Nn)            // 40000
#define NODES_PAD 40064          // 313 * 128
#define RSQRT_DH 0.17677669529663687f

// ---------------- scratch (device globals; zero-init, no allocation) ---------
__device__ float2 g_qka[NODES];          // {qa, ka} packed
__device__ float g_att_sum[NODES];
__device__ float g_att_exp[Ee];
__device__ int   g_counts[NODES];
__device__ int   g_offsets[NODES + 1];
__device__ int   g_cursor[NODES];
__device__ int4  g_edge[Ee];             // {e, dst_node, alpha_bits, 0} sorted by src
__device__ float g_Mx[NODES_PAD * Dd];   // Σ alpha * x[dst]
__device__ float g_Me[NODES_PAD * DE];   // Σ alpha * e_emb[e]
__device__ float g_sA[NODES_PAD];        // Σ alpha
__device__ float g_wqa[Dd];
__device__ float g_wka[Dd];
__device__ float g_wewa[DE];
__device__ float g_bvev[Dd];             // bv + bev
__device__ float g_cc;                   // (bq+bk+bew)·Wa

// ---------------- cp.async helpers ------------------------------------------
__device__ __forceinline__ void cp16(void* dst, const void* src) {
    uint32_t d = (uint32_t)__cvta_generic_to_shared(dst);
    asm volatile("cp.async.cg.shared.global [%0], [%1], 16;" :: "r"(d), "l"(src));
}
#define CP_COMMIT() asm volatile("cp.async.commit_group;")
#define CP_WAIT(n)  asm volatile("cp.async.wait_group %0;" :: "n"(n))

// ---------------- K0: fold Wa into projections; bias combos -----------------
__global__ void k_prep(const float* __restrict__ Wq, const float* __restrict__ Wk,
                       const float* __restrict__ Wew,
                       const float* __restrict__ bq, const float* __restrict__ bk,
                       const float* __restrict__ bew, const float* __restrict__ Wa,
                       const float* __restrict__ bv, const float* __restrict__ bev) {
    int i = threadIdx.x;  // 128 threads
    float a = 0.f, b = 0.f;
    for (int j = 0; j < Dd; j++) {
        float wa = Wa[j];
        a += Wq[i * Dd + j] * wa;
        b += Wk[i * Dd + j] * wa;
    }
    g_wqa[i] = a;
    g_wka[i] = b;
    g_bvev[i] = bv[i] + bev[i];
    if (i < DE) {
        float c = 0.f;
        for (int j = 0; j < Dd; j++) c += Wew[i * Dd + j] * Wa[j];
        g_wewa[i] = c;
    }
    if (i == 0) {
        float cc = 0.f;
        for (int j = 0; j < Dd; j++) cc += (bq[j] + bk[j] + bew[j]) * Wa[j];
        g_cc = cc;
    }
}

// ---------------- K1: zero accumulators --------------------------------------
__global__ void k_zero() {
    int i = blockIdx.x * blockDim.x + threadIdx.x;
    if (i < NODES) { g_att_sum[i] = 0.f; g_counts[i] = 0; }
}

// ---------------- K2: per-node attention scalars {qa, ka} --------------------
__global__ void k_qaka(const float* __restrict__ x) {
    int warp = (blockIdx.x * blockDim.x + threadIdx.x) >> 5;
    int lane = threadIdx.x & 31;
    if (warp >= NODES) return;
    float4 xv = *(const float4*)&x[(size_t)warp * Dd + lane * 4];
    float4 wq = *(const float4*)&g_wqa[lane * 4];
    float4 wk = *(const float4*)&g_wka[lane * 4];
    float a = xv.x * wq.x + xv.y * wq.y + xv.z * wq.z + xv.w * wq.w;
    float b = xv.x * wk.x + xv.y * wk.y + xv.z * wk.z + xv.w * wk.w;
    #pragma unroll
    for (int off = 16; off > 0; off >>= 1) {
        a += __shfl_xor_sync(0xffffffffu, a, off);
        b += __shfl_xor_sync(0xffffffffu, b, off);
    }
    if (lane == 0) g_qka[warp] = make_float2(a, b);
}

// ---------------- K3: edge pass — exp(logit), segment sums, histogram --------
// 2 edges per thread for MLP; packed float2 qka load halves random loads.
__global__ void k_edge1(const int* __restrict__ ei, const float* __restrict__ e_emb,
                        const int* __restrict__ bi) {
    __shared__ float ws4[DE];
    __shared__ float s_cc;
    if (threadIdx.x < DE) ws4[threadIdx.x] = g_wewa[threadIdx.x];
    if (threadIdx.x == 0) s_cc = g_cc;
    __syncthreads();
    int base = (blockIdx.x * blockDim.x + threadIdx.x) * 2;
    #pragma unroll
    for (int u = 0; u < 2; u++) {
        int e = base + u;
        if (e >= Ee) return;
        int src = ei[e];
        int dst = ei[Ee + e];
        int b   = bi[e];
        const float4* ep = (const float4*)(e_emb + (size_t)e * DE);
        float dot = 0.f;
        #pragma unroll
        for (int i = 0; i < 8; i++) {
            float4 v = ep[i];
            dot += v.x * ws4[i * 4 + 0] + v.y * ws4[i * 4 + 1] +
                   v.z * ws4[i * 4 + 2] + v.w * ws4[i * 4 + 3];
        }
        float2 qs = g_qka[b * Nn + src];
        float2 kd = g_qka[b * Nn + dst];
        float logit = (qs.x + kd.y + dot + s_cc) * RSQRT_DH;
        float ex = __expf(logit);
        g_att_exp[e] = ex;
        atomicAdd(&g_att_sum[b * Nn + dst], ex);
        atomicAdd(&g_counts[b * Nn + src], 1);
    }
}

// ---------------- K4: single-block exclusive scan of counts ------------------
#define SCAN_T 1024
#define SCAN_CH 40
__global__ void k_scan() {
    __shared__ int sh[SCAN_T];
    int t = threadIdx.x;
    int start = t * SCAN_CH;
    int end = min(start + SCAN_CH, NODES);
    int s = 0;
    for (int i = start; i < end; i++) s += g_counts[i];
    sh[t] = s;
    __syncthreads();
    for (int off = 1; off < SCAN_T; off <<= 1) {
        int v = (t >= off) ? sh[t - off] : 0;
        __syncthreads();
        sh[t] += v;
        __syncthreads();
    }
    int run = (t == 0) ? 0 : sh[t - 1];
    for (int i = start; i < end; i++) {
        g_offsets[i] = run;
        g_cursor[i] = run;
        run += g_counts[i];
    }
    if (t == SCAN_T - 1) g_offsets[NODES] = sh[SCAN_T - 1];
}

// ---------------- K5: scatter packed {e, dst, alpha} into src order ----------
__global__ void k_scatter(const int* __restrict__ ei, const int* __restrict__ bi) {
    int base = (blockIdx.x * blockDim.x + threadIdx.x) * 2;
    #pragma unroll
    for (int u = 0; u < 2; u++) {
        int e = base + u;
        if (e >= Ee) return;
        int b = bi[e];
        int key  = b * Nn + ei[e];        // source node (sort key)
        int dstn = b * Nn + ei[Ee + e];   // destination node
        float alpha = g_att_exp[e] / (g_att_sum[dstn] + 1e-9f);
        int pos = atomicAdd(&g_cursor[key], 1);
        int4 pk;
        pk.x = e;
        pk.y = dstn;
        pk.z = __float_as_int(alpha);
        pk.w = 0;
        g_edge[pos] = pk;
    }
}

// ---------------- K6: gather moments, one warp per src node ------------------
// Quad-batched: 4 edge records loaded, then 4 independent x-row loads + 4
// e_emb loads issued before accumulation -> MLP ~8 on the random-load chain.
// 4 warps per block (128 threads) -> more resident CTAs, more cross-warp MLP.
__global__ __launch_bounds__(128) void k_gather(const float* __restrict__ x,
                                                const float* __restrict__ e_emb) {
    int s = blockIdx.x * 4 + (threadIdx.x >> 5);
    int lane = threadIdx.x & 31;
    if (s >= NODES) return;

    int start = g_offsets[s];
    int end   = g_offsets[s + 1];

    float4 accx = make_float4(0.f, 0.f, 0.f, 0.f);
    float4 acce = make_float4(0.f, 0.f, 0.f, 0.f);
    float  accA = 0.f;

    int i = start;
    for (; i + 4 <= end; i += 4) {
        int4 m0 = g_edge[i + 0];
        int4 m1 = g_edge[i + 1];
        int4 m2 = g_edge[i + 2];
        int4 m3 = g_edge[i + 3];
        float4 v0 = *(const float4*)&x[(size_t)m0.y * Dd + lane * 4];
        float4 v1 = *(const float4*)&x[(size_t)m1.y * Dd + lane * 4];
        float4 v2 = *(const float4*)&x[(size_t)m2.y * Dd + lane * 4];
        float4 v3 = *(const float4*)&x[(size_t)m3.y * Dd + lane * 4];
        float4 e0 = make_float4(0.f,0.f,0.f,0.f), e1 = e0, e2 = e0, e3 = e0;
        if (lane < 8) {
            e0 = *(const float4*)&e_emb[(size_t)m0.x * DE + lane * 4];
            e1 = *(const float4*)&e_emb[(size_t)m1.x * DE + lane * 4];
            e2 = *(const float4*)&e_emb[(size_t)m2.x * DE + lane * 4];
            e3 = *(const float4*)&e_emb[(size_t)m3.x * DE + lane * 4];
        }
        float a0 = __int_as_float(m0.z), a1 = __int_as_float(m1.z);
        float a2 = __int_as_float(m2.z), a3 = __int_as_float(m3.z);
        accx.x += a0*v0.x + a1*v1.x + a2*v2.x + a3*v3.x;
        accx.y += a0*v0.y + a1*v1.y + a2*v2.y + a3*v3.y;
        accx.z += a0*v0.z + a1*v1.z + a2*v2.z + a3*v3.z;
        accx.w += a0*v0.w + a1*v1.w + a2*v2.w + a3*v3.w;
        acce.x += a0*e0.x + a1*e1.x + a2*e2.x + a3*e3.x;
        acce.y += a0*e0.y + a1*e1.y + a2*e2.y + a3*e3.y;
        acce.z += a0*e0.z + a1*e1.z + a2*e2.z + a3*e3.z;
        acce.w += a0*e0.w + a1*e1.w + a2*e2.w + a3*e3.w;
        accA += a0 + a1 + a2 + a3;
    }
    for (; i < end; i++) {
        int4 m = g_edge[i];
        float a = __int_as_float(m.z);
        float4 v = *(const float4*)&x[(size_t)m.y * Dd + lane * 4];
        float4 ev = make_float4(0.f, 0.f, 0.f, 0.f);
        if (lane < 8) ev = *(const float4*)&e_emb[(size_t)m.x * DE + lane * 4];
        accx.x += a * v.x; accx.y += a * v.y;
        accx.z += a * v.z; accx.w += a * v.w;
        acce.x += a * ev.x; acce.y += a * ev.y;
        acce.z += a * ev.z; acce.w += a * ev.w;
        accA += a;
    }

    *(float4*)&g_Mx[(size_t)s * Dd + lane * 4] = accx;
    if (lane < 8) *(float4*)&g_Me[(size_t)s * DE + lane * 4] = acce;
    if (lane == 0) g_sA[s] = accA;
}

// ---------------- K7: fused epilogue GEMM  out = [Mx|Me]@[Wv;Wev] + sA⊗(bv+bev)
#define OB_M 128
#define OB_K 16
#define NTILES 10   // 8 tiles from Mx/Wv (K=128) + 2 tiles from Me/Wev (K=32)
__global__ __launch_bounds__(256) void k_out(const float* __restrict__ Wv,
                                             const float* __restrict__ Wev,
                                             float* __restrict__ out) {
    __shared__ float As[2][OB_M * OB_K];   // row-major [m][k]
    __shared__ float Bs[2][OB_K * Dd];     // [k][n]
    __shared__ float sA_sh[OB_M];
    __shared__ float bb_sh[Dd];

    int t  = threadIdx.x;
    int m0 = blockIdx.x * OB_M;
    if (t < OB_M) {
        sA_sh[t] = g_sA[m0 + t];   // padded array, rows >= NODES are zero
        bb_sh[t] = g_bvev[t];
    }

    auto issue = [&](int stage, int tile) {
        #pragma unroll
        for (int it = 0; it < 2; it++) {
            int q = t + it * 256;
            int m = q >> 2, kq = q & 3;
            const float* srcA = (tile < 8)
                ? &g_Mx[(size_t)(m0 + m) * Dd + tile * OB_K + kq * 4]
                : &g_Me[(size_t)(m0 + m) * DE + (tile - 8) * OB_K + kq * 4];
            cp16(&As[stage][m * OB_K + kq * 4], srcA);
            int k = q >> 5, c4 = q & 31;
            const float* srcB = (tile < 8)
                ? &Wv[(size_t)(tile * OB_K + k) * Dd + c4 * 4]
                : &Wev[(size_t)((tile - 8) * OB_K + k) * Dd + c4 * 4];
            cp16(&Bs[stage][k * Dd + c4 * 4], srcB);
        }
    };

    issue(0, 0);
    CP_COMMIT();

    float acc[8][8];
    #pragma unroll
    for (int i = 0; i < 8; i++)
        #pragma unroll
        for (int j = 0; j < 8; j++) acc[i][j] = 0.f;

    int tx = t & 15, ty = t >> 4;

    for (int tile = 0; tile < NTILES; tile++) {
        int cur = tile & 1, nxt = cur ^ 1;
        if (tile + 1 < NTILES) {
            issue(nxt, tile + 1);
            CP_COMMIT();
            CP_WAIT(1);
        } else {
            CP_WAIT(0);
        }
        __syncthreads();
        #pragma unroll
        for (int k = 0; k < OB_K; k++) {
            float xv[8];
            #pragma unroll
            for (int i = 0; i < 8; i++) xv[i] = As[cur][(ty * 8 + i) * OB_K + k];
            float4 w0 = *(float4*)&Bs[cur][k * Dd + tx * 8];
            float4 w1 = *(float4*)&Bs[cur][k * Dd + tx * 8 + 4];
            #pragma unroll
            for (int i = 0; i < 8; i++) {
                acc[i][0] += xv[i] * w0.x;
                acc[i][1] += xv[i] * w0.y;
                acc[i][2] += xv[i] * w0.z;
                acc[i][3] += xv[i] * w0.w;
                acc[i][4] += xv[i] * w1.x;
                acc[i][5] += xv[i] * w1.y;
                acc[i][6] += xv[i] * w1.z;
                acc[i][7] += xv[i] * w1.w;
            }
        }
        __syncthreads();
    }

    #pragma unroll
    for (int i = 0; i < 8; i++) {
        int r = m0 + ty * 8 + i;
        if (r < NODES) {
            float sa = sA_sh[ty * 8 + i];
            int c0 = tx * 8;
            float4 o0, o1;
            o0.x = acc[i][0] + sa * bb_sh[c0 + 0];
            o0.y = acc[i][1] + sa * bb_sh[c0 + 1];
            o0.z = acc[i][2] + sa * bb_sh[c0 + 2];
            o0.w = acc[i][3] + sa * bb_sh[c0 + 3];
            o1.x = acc[i][4] + sa * bb_sh[c0 + 4];
            o1.y = acc[i][5] + sa * bb_sh[c0 + 5];
            o1.z = acc[i][6] + sa * bb_sh[c0 + 6];
            o1.w = acc[i][7] + sa * bb_sh[c0 + 7];
            *(float4*)&out[(size_t)r * Dd + c0]     = o0;
            *(float4*)&out[(size_t)r * Dd + c0 + 4] = o1;
        }
    }
}

// ---------------- launch ------------------------------------------------------
extern "C" void kernel_launch(void* const* d_in, const int* in_sizes, int n_in,
                              void* d_out, int out_size) {
    const float* x     = (const float*)d_in[0];
    const int*   ei    = (const int*)  d_in[1];
    const float* e_emb = (const float*)d_in[2];
    const int*   bi    = (const int*)  d_in[3];
    const float* Wq    = (const float*)d_in[4];
    const float* bq    = (const float*)d_in[5];
    const float* Wk    = (const float*)d_in[6];
    const float* bk    = (const float*)d_in[7];
    const float* Wv    = (const float*)d_in[8];
    const float* bv    = (const float*)d_in[9];
    const float* Wew   = (const float*)d_in[10];
    const float* bew   = (const float*)d_in[11];
    const float* Wev   = (const float*)d_in[12];
    const float* bev   = (const float*)d_in[13];
    const float* Wa    = (const float*)d_in[14];
    float* out = (float*)d_out;

    k_prep<<<1, 128>>>(Wq, Wk, Wew, bq, bk, bew, Wa, bv, bev);
    k_zero<<<(NODES + 255) / 256, 256>>>();
    k_qaka<<<(NODES + 7) / 8, 256>>>(x);
    k_edge1<<<(Ee + 511) / 512, 256>>>(ei, e_emb, bi);
    k_scan<<<1, SCAN_T>>>();
    k_scatter<<<(Ee + 511) / 512, 256>>>(ei, bi);
    k_gather<<<(NODES + 3) / 4, 128>>>(x, e_emb);
    k_out<<<NODES_PAD / OB_M, 256>>>(Wv, Wev, out);
}

// round 8
// speedup vs baseline: 1.3254x; 1.0389x over previous
#include <cuda_runtime.h>
#include <cuda_fp16.h>
#include <math.h>
#include <stdint.h>

#define Bb 4
#define Nn 10000
#define Dd 128
#define DE 32
#define Ee 640000
#define NODES (Bb*Nn)            // 40000
#define NODES_PAD 40064          // 313 * 128
#define RSQRT_DH 0.17677669529663687f

// ---------------- scratch (device globals; zero-init, no allocation) ---------
__device__ float2 g_qka[NODES];          // {qa, ka} packed
__device__ float g_att_sum[NODES];
__device__ float g_att_exp[Ee];
__device__ int   g_counts[NODES];
__device__ int   g_offsets[NODES + 1];
__device__ int   g_cursor[NODES];
__device__ int4  g_edge[Ee];             // {e, dst_node, alpha_bits, 0} sorted by src
__device__ __half g_xh[NODES * Dd];      // fp16 copy of x (10 MB, L2-resident)
__device__ float g_Mx[NODES_PAD * Dd];   // Σ alpha * x[dst]
__device__ float g_Me[NODES_PAD * DE];   // Σ alpha * e_emb[e]
__device__ float g_sA[NODES_PAD];        // Σ alpha
__device__ float g_wqa[Dd];
__device__ float g_wka[Dd];
__device__ float g_wewa[DE];
__device__ float g_bvev[Dd];             // bv + bev
__device__ float g_cc;                   // (bq+bk+bew)·Wa

// ---------------- cp.async helpers ------------------------------------------
__device__ __forceinline__ void cp16(void* dst, const void* src) {
    uint32_t d = (uint32_t)__cvta_generic_to_shared(dst);
    asm volatile("cp.async.cg.shared.global [%0], [%1], 16;" :: "r"(d), "l"(src));
}
#define CP_COMMIT() asm volatile("cp.async.commit_group;")
#define CP_WAIT(n)  asm volatile("cp.async.wait_group %0;" :: "n"(n))

__device__ __forceinline__ float4 h4tof4(uint2 r) {
    __half2* p = (__half2*)&r;
    float2 lo = __half22float2(p[0]);
    float2 hi = __half22float2(p[1]);
    return make_float4(lo.x, lo.y, hi.x, hi.y);
}

// ---------------- K0: fold Wa into projections; bias combos -----------------
__global__ void k_prep(const float* __restrict__ Wq, const float* __restrict__ Wk,
                       const float* __restrict__ Wew,
                       const float* __restrict__ bq, const float* __restrict__ bk,
                       const float* __restrict__ bew, const float* __restrict__ Wa,
                       const float* __restrict__ bv, const float* __restrict__ bev) {
    int i = threadIdx.x;  // 128 threads
    float a = 0.f, b = 0.f;
    for (int j = 0; j < Dd; j++) {
        float wa = Wa[j];
        a += Wq[i * Dd + j] * wa;
        b += Wk[i * Dd + j] * wa;
    }
    g_wqa[i] = a;
    g_wka[i] = b;
    g_bvev[i] = bv[i] + bev[i];
    if (i < DE) {
        float c = 0.f;
        for (int j = 0; j < Dd; j++) c += Wew[i * Dd + j] * Wa[j];
        g_wewa[i] = c;
    }
    if (i == 0) {
        float cc = 0.f;
        for (int j = 0; j < Dd; j++) cc += (bq[j] + bk[j] + bew[j]) * Wa[j];
        g_cc = cc;
    }
}

// ---------------- K1: zero accumulators --------------------------------------
__global__ void k_zero() {
    int i = blockIdx.x * blockDim.x + threadIdx.x;
    if (i < NODES) { g_att_sum[i] = 0.f; g_counts[i] = 0; }
}

// ---------------- K1b: convert x to fp16 -------------------------------------
__global__ void k_xhalf(const float* __restrict__ x) {
    int i = blockIdx.x * blockDim.x + threadIdx.x;   // one float4 per thread
    if (i >= NODES * Dd / 4) return;
    float4 v = *(const float4*)&x[i * 4];
    __half2 h0 = __floats2half2_rn(v.x, v.y);
    __half2 h1 = __floats2half2_rn(v.z, v.w);
    uint2 packed;
    packed.x = *(uint32_t*)&h0;
    packed.y = *(uint32_t*)&h1;
    *(uint2*)&g_xh[i * 4] = packed;
}

// ---------------- K2: per-node attention scalars {qa, ka} --------------------
__global__ void k_qaka(const float* __restrict__ x) {
    int warp = (blockIdx.x * blockDim.x + threadIdx.x) >> 5;
    int lane = threadIdx.x & 31;
    if (warp >= NODES) return;
    float4 xv = *(const float4*)&x[(size_t)warp * Dd + lane * 4];
    float4 wq = *(const float4*)&g_wqa[lane * 4];
    float4 wk = *(const float4*)&g_wka[lane * 4];
    float a = xv.x * wq.x + xv.y * wq.y + xv.z * wq.z + xv.w * wq.w;
    float b = xv.x * wk.x + xv.y * wk.y + xv.z * wk.z + xv.w * wk.w;
    #pragma unroll
    for (int off = 16; off > 0; off >>= 1) {
        a += __shfl_xor_sync(0xffffffffu, a, off);
        b += __shfl_xor_sync(0xffffffffu, b, off);
    }
    if (lane == 0) g_qka[warp] = make_float2(a, b);
}

// ---------------- K3: edge pass — warp-cooperative coalesced e_emb dot -------
// 8 lanes per edge, 4 edges per LDG.128 (512B contiguous per instr -> 4 L1
// wavefronts instead of 32). Dots staged in smem, then 1 edge/lane phase for
// the random qka loads + exp + atomics. 32 edges per warp.
__global__ __launch_bounds__(256) void k_edge1(const int* __restrict__ ei,
                                               const float* __restrict__ e_emb,
                                               const int* __restrict__ bi) {
    __shared__ float ws4[DE];
    __shared__ float s_cc;
    __shared__ float sdot[8][32];
    int t = threadIdx.x;
    if (t < DE) ws4[t] = g_wewa[t];
    if (t == 0) s_cc = g_cc;
    __syncthreads();

    int wid  = t >> 5;
    int lane = t & 31;
    int base = (blockIdx.x * 8 + wid) * 32;      // 32 edges per warp

    // Phase B index loads issued early (independent of phase A)
    int e_mine = base + lane;
    int src = ei[e_mine];
    int dst = ei[Ee + e_mine];
    int b   = bi[e_mine];

    // Phase A: cooperative dot products
    int oct  = lane >> 3;       // 0..3: which edge in the quad
    int sub  = lane & 7;        // 0..7: which float4 of that edge
    float w0 = ws4[sub * 4 + 0], w1 = ws4[sub * 4 + 1];
    float w2 = ws4[sub * 4 + 2], w3 = ws4[sub * 4 + 3];
    #pragma unroll
    for (int g = 0; g < 8; g++) {
        int e4 = base + g * 4 + oct;
        float4 v = *(const float4*)&e_emb[(size_t)e4 * DE + sub * 4];
        float d = v.x * w0 + v.y * w1 + v.z * w2 + v.w * w3;
        d += __shfl_xor_sync(0xffffffffu, d, 4);
        d += __shfl_xor_sync(0xffffffffu, d, 2);
        d += __shfl_xor_sync(0xffffffffu, d, 1);
        if (sub == 0) sdot[wid][g * 4 + oct] = d;
    }
    __syncwarp();

    // Phase B: one edge per lane
    float dot = sdot[wid][lane];
    float2 qs = g_qka[b * Nn + src];
    float2 kd = g_qka[b * Nn + dst];
    float logit = (qs.x + kd.y + dot + s_cc) * RSQRT_DH;
    float ex = __expf(logit);
    g_att_exp[e_mine] = ex;
    atomicAdd(&g_att_sum[b * Nn + dst], ex);
    atomicAdd(&g_counts[b * Nn + src], 1);
}

// ---------------- K4: single-block exclusive scan of counts ------------------
#define SCAN_T 1024
#define SCAN_CH 40
__global__ void k_scan() {
    __shared__ int sh[SCAN_T];
    int t = threadIdx.x;
    int start = t * SCAN_CH;
    int end = min(start + SCAN_CH, NODES);
    int s = 0;
    for (int i = start; i < end; i++) s += g_counts[i];
    sh[t] = s;
    __syncthreads();
    for (int off = 1; off < SCAN_T; off <<= 1) {
        int v = (t >= off) ? sh[t - off] : 0;
        __syncthreads();
        sh[t] += v;
        __syncthreads();
    }
    int run = (t == 0) ? 0 : sh[t - 1];
    for (int i = start; i < end; i++) {
        g_offsets[i] = run;
        g_cursor[i] = run;
        run += g_counts[i];
    }
    if (t == SCAN_T - 1) g_offsets[NODES] = sh[SCAN_T - 1];
}

// ---------------- K5: scatter packed {e, dst, alpha} into src order ----------
__global__ void k_scatter(const int* __restrict__ ei, const int* __restrict__ bi) {
    int base = (blockIdx.x * blockDim.x + threadIdx.x) * 2;
    #pragma unroll
    for (int u = 0; u < 2; u++) {
        int e = base + u;
        if (e >= Ee) return;
        int b = bi[e];
        int key  = b * Nn + ei[e];        // source node (sort key)
        int dstn = b * Nn + ei[Ee + e];   // destination node
        float alpha = g_att_exp[e] / (g_att_sum[dstn] + 1e-9f);
        int pos = atomicAdd(&g_cursor[key], 1);
        int4 pk;
        pk.x = e;
        pk.y = dstn;
        pk.z = __float_as_int(alpha);
        pk.w = 0;
        g_edge[pos] = pk;
    }
}

// ---------------- K6: gather moments, one warp per src node ------------------
// Quad-batched; x rows read as fp16 (256B/row via one uint2 per lane) to halve
// the dominant L2 gather traffic. Accumulation stays fp32.
__global__ __launch_bounds__(128) void k_gather(const float* __restrict__ e_emb) {
    int s = blockIdx.x * 4 + (threadIdx.x >> 5);
    int lane = threadIdx.x & 31;
    if (s >= NODES) return;

    int start = g_offsets[s];
    int end   = g_offsets[s + 1];

    float4 accx = make_float4(0.f, 0.f, 0.f, 0.f);
    float4 acce = make_float4(0.f, 0.f, 0.f, 0.f);
    float  accA = 0.f;

    int i = start;
    for (; i + 4 <= end; i += 4) {
        int4 m0 = g_edge[i + 0];
        int4 m1 = g_edge[i + 1];
        int4 m2 = g_edge[i + 2];
        int4 m3 = g_edge[i + 3];
        uint2 r0 = *(const uint2*)&g_xh[(size_t)m0.y * Dd + lane * 4];
        uint2 r1 = *(const uint2*)&g_xh[(size_t)m1.y * Dd + lane * 4];
        uint2 r2 = *(const uint2*)&g_xh[(size_t)m2.y * Dd + lane * 4];
        uint2 r3 = *(const uint2*)&g_xh[(size_t)m3.y * Dd + lane * 4];
        float4 e0 = make_float4(0.f,0.f,0.f,0.f), e1 = e0, e2 = e0, e3 = e0;
        if (lane < 8) {
            e0 = *(const float4*)&e_emb[(size_t)m0.x * DE + lane * 4];
            e1 = *(const float4*)&e_emb[(size_t)m1.x * DE + lane * 4];
            e2 = *(const float4*)&e_emb[(size_t)m2.x * DE + lane * 4];
            e3 = *(const float4*)&e_emb[(size_t)m3.x * DE + lane * 4];
        }
        float a0 = __int_as_float(m0.z), a1 = __int_as_float(m1.z);
        float a2 = __int_as_float(m2.z), a3 = __int_as_float(m3.z);
        float4 v0 = h4tof4(r0), v1 = h4tof4(r1), v2 = h4tof4(r2), v3 = h4tof4(r3);
        accx.x += a0*v0.x + a1*v1.x + a2*v2.x + a3*v3.x;
        accx.y += a0*v0.y + a1*v1.y + a2*v2.y + a3*v3.y;
        accx.z += a0*v0.z + a1*v1.z + a2*v2.z + a3*v3.z;
        accx.w += a0*v0.w + a1*v1.w + a2*v2.w + a3*v3.w;
        acce.x += a0*e0.x + a1*e1.x + a2*e2.x + a3*e3.x;
        acce.y += a0*e0.y + a1*e1.y + a2*e2.y + a3*e3.y;
        acce.z += a0*e0.z + a1*e1.z + a2*e2.z + a3*e3.z;
        acce.w += a0*e0.w + a1*e1.w + a2*e2.w + a3*e3.w;
        accA += a0 + a1 + a2 + a3;
    }
    for (; i < end; i++) {
        int4 m = g_edge[i];
        float a = __int_as_float(m.z);
        uint2 r = *(const uint2*)&g_xh[(size_t)m.y * Dd + lane * 4];
        float4 ev = make_float4(0.f, 0.f, 0.f, 0.f);
        if (lane < 8) ev = *(const float4*)&e_emb[(size_t)m.x * DE + lane * 4];
        float4 v = h4tof4(r);
        accx.x += a * v.x; accx.y += a * v.y;
        accx.z += a * v.z; accx.w += a * v.w;
        acce.x += a * ev.x; acce.y += a * ev.y;
        acce.z += a * ev.z; acce.w += a * ev.w;
        accA += a;
    }

    *(float4*)&g_Mx[(size_t)s * Dd + lane * 4] = accx;
    if (lane < 8) *(float4*)&g_Me[(size_t)s * DE + lane * 4] = acce;
    if (lane == 0) g_sA[s] = accA;
}

// ---------------- K7: fused epilogue GEMM  out = [Mx|Me]@[Wv;Wev] + sA⊗(bv+bev)
#define OB_M 128
#define OB_K 16
#define NTILES 10   // 8 tiles from Mx/Wv (K=128) + 2 tiles from Me/Wev (K=32)
__global__ __launch_bounds__(256) void k_out(const float* __restrict__ Wv,
                                             const float* __restrict__ Wev,
                                             float* __restrict__ out) {
    __shared__ float As[2][OB_M * OB_K];   // row-major [m][k]
    __shared__ float Bs[2][OB_K * Dd];     // [k][n]
    __shared__ float sA_sh[OB_M];
    __shared__ float bb_sh[Dd];

    int t  = threadIdx.x;
    int m0 = blockIdx.x * OB_M;
    if (t < OB_M) {
        sA_sh[t] = g_sA[m0 + t];   // padded array, rows >= NODES are zero
        bb_sh[t] = g_bvev[t];
    }

    auto issue = [&](int stage, int tile) {
        #pragma unroll
        for (int it = 0; it < 2; it++) {
            int q = t + it * 256;
            int m = q >> 2, kq = q & 3;
            const float* srcA = (tile < 8)
                ? &g_Mx[(size_t)(m0 + m) * Dd + tile * OB_K + kq * 4]
                : &g_Me[(size_t)(m0 + m) * DE + (tile - 8) * OB_K + kq * 4];
            cp16(&As[stage][m * OB_K + kq * 4], srcA);
            int k = q >> 5, c4 = q & 31;
            const float* srcB = (tile < 8)
                ? &Wv[(size_t)(tile * OB_K + k) * Dd + c4 * 4]
                : &Wev[(size_t)((tile - 8) * OB_K + k) * Dd + c4 * 4];
            cp16(&Bs[stage][k * Dd + c4 * 4], srcB);
        }
    };

    issue(0, 0);
    CP_COMMIT();

    float acc[8][8];
    #pragma unroll
    for (int i = 0; i < 8; i++)
        #pragma unroll
        for (int j = 0; j < 8; j++) acc[i][j] = 0.f;

    int tx = t & 15, ty = t >> 4;

    for (int tile = 0; tile < NTILES; tile++) {
        int cur = tile & 1, nxt = cur ^ 1;
        if (tile + 1 < NTILES) {
            issue(nxt, tile + 1);
            CP_COMMIT();
            CP_WAIT(1);
        } else {
            CP_WAIT(0);
        }
        __syncthreads();
        #pragma unroll
        for (int k = 0; k < OB_K; k++) {
            float xv[8];
            #pragma unroll
            for (int i = 0; i < 8; i++) xv[i] = As[cur][(ty * 8 + i) * OB_K + k];
            float4 w0 = *(float4*)&Bs[cur][k * Dd + tx * 8];
            float4 w1 = *(float4*)&Bs[cur][k * Dd + tx * 8 + 4];
            #pragma unroll
            for (int i = 0; i < 8; i++) {
                acc[i][0] += xv[i] * w0.x;
                acc[i][1] += xv[i] * w0.y;
                acc[i][2] += xv[i] * w0.z;
                acc[i][3] += xv[i] * w0.w;
                acc[i][4] += xv[i] * w1.x;
                acc[i][5] += xv[i] * w1.y;
                acc[i][6] += xv[i] * w1.z;
                acc[i][7] += xv[i] * w1.w;
            }
        }
        __syncthreads();
    }

    #pragma unroll
    for (int i = 0; i < 8; i++) {
        int r = m0 + ty * 8 + i;
        if (r < NODES) {
            float sa = sA_sh[ty * 8 + i];
            int c0 = tx * 8;
            float4 o0, o1;
            o0.x = acc[i][0] + sa * bb_sh[c0 + 0];
            o0.y = acc[i][1] + sa * bb_sh[c0 + 1];
            o0.z = acc[i][2] + sa * bb_sh[c0 + 2];
            o0.w = acc[i][3] + sa * bb_sh[c0 + 3];
            o1.x = acc[i][4] + sa * bb_sh[c0 + 4];
            o1.y = acc[i][5] + sa * bb_sh[c0 + 5];
            o1.z = acc[i][6] + sa * bb_sh[c0 + 6];
            o1.w = acc[i][7] + sa * bb_sh[c0 + 7];
            *(float4*)&out[(size_t)r * Dd + c0]     = o0;
            *(float4*)&out[(size_t)r * Dd + c0 + 4] = o1;
        }
    }
}

// ---------------- launch ------------------------------------------------------
extern "C" void kernel_launch(void* const* d_in, const int* in_sizes, int n_in,
                              void* d_out, int out_size) {
    const float* x     = (const float*)d_in[0];
    const int*   ei    = (const int*)  d_in[1];
    const float* e_emb = (const float*)d_in[2];
    const int*   bi    = (const int*)  d_in[3];
    const float* Wq    = (const float*)d_in[4];
    const float* bq    = (const float*)d_in[5];
    const float* Wk    = (const float*)d_in[6];
    const float* bk    = (const float*)d_in[7];
    const float* Wv    = (const float*)d_in[8];
    const float* bv    = (const float*)d_in[9];
    const float* Wew   = (const float*)d_in[10];
    const float* bew   = (const float*)d_in[11];
    const float* Wev   = (const float*)d_in[12];
    const float* bev   = (const float*)d_in[13];
    const float* Wa    = (const float*)d_in[14];
    float* out = (float*)d_out;

    k_prep<<<1, 128>>>(Wq, Wk, Wew, bq, bk, bew, Wa, bv, bev);
    k_zero<<<(NODES + 255) / 256, 256>>>();
    k_xhalf<<<(NODES * Dd / 4 + 255) / 256, 256>>>(x);
    k_qaka<<<(NODES + 7) / 8, 256>>>(x);
    k_edge1<<<Ee / 256, 256>>>(ei, e_emb, bi);   // 640000 = 2500 * 256 exactly
    k_scan<<<1, SCAN_T>>>();
    k_scatter<<<(Ee + 511) / 512, 256>>>(ei, bi);
    k_gather<<<(NODES + 3) / 4, 128>>>(e_emb);
    k_out<<<NODES_PAD / OB_M, 256>>>(Wv, Wev, out);
}

// round 9
// speedup vs baseline: 1.3256x; 1.0001x over previous
#include <cuda_runtime.h>
#include <cuda_fp16.h>
#include <math.h>
#include <stdint.h>

#define Bb 4
#define Nn 10000
#define Dd 128
#define DE 32
#define Ee 640000
#define NODES (Bb*Nn)            // 40000
#define NODES_PAD 40064          // 313 * 128
#define RSQRT_DH 0.17677669529663687f

// ---------------- scratch (device globals; zero-init, no allocation) ---------
__device__ float2 g_qka[NODES];          // {qa, ka} packed
__device__ float g_att_sum[NODES];
__device__ int   g_counts[NODES];
__device__ int   g_offsets[NODES + 1];
__device__ int   g_cursor[NODES];
__device__ int4  g_edge[Ee];             // {e, dst_node, exp_bits, 0} sorted by src
__device__ __half g_xh[NODES * Dd];      // fp16 copy of x (10 MB, L2-resident)
__device__ float g_Mx[NODES_PAD * Dd];   // Σ alpha * x[dst]
__device__ float g_Me[NODES_PAD * DE];   // Σ alpha * e_emb[e]
__device__ float g_sA[NODES_PAD];        // Σ alpha
__device__ float g_wqa[Dd];
__device__ float g_wka[Dd];
__device__ float g_wewa[DE];
__device__ float g_bvev[Dd];             // bv + bev
__device__ float g_cc;                   // (bq+bk+bew)·Wa

// ---------------- cp.async helpers ------------------------------------------
__device__ __forceinline__ void cp16(void* dst, const void* src) {
    uint32_t d = (uint32_t)__cvta_generic_to_shared(dst);
    asm volatile("cp.async.cg.shared.global [%0], [%1], 16;" :: "r"(d), "l"(src));
}
#define CP_COMMIT() asm volatile("cp.async.commit_group;")
#define CP_WAIT(n)  asm volatile("cp.async.wait_group %0;" :: "n"(n))

__device__ __forceinline__ float4 h4tof4(uint2 r) {
    __half2* p = (__half2*)&r;
    float2 lo = __half22float2(p[0]);
    float2 hi = __half22float2(p[1]);
    return make_float4(lo.x, lo.y, hi.x, hi.y);
}

// ---------------- K0: fold Wa into projections; bias combos -----------------
__global__ void k_prep(const float* __restrict__ Wq, const float* __restrict__ Wk,
                       const float* __restrict__ Wew,
                       const float* __restrict__ bq, const float* __restrict__ bk,
                       const float* __restrict__ bew, const float* __restrict__ Wa,
                       const float* __restrict__ bv, const float* __restrict__ bev) {
    int i = threadIdx.x;  // 128 threads
    float a = 0.f, b = 0.f;
    for (int j = 0; j < Dd; j++) {
        float wa = Wa[j];
        a += Wq[i * Dd + j] * wa;
        b += Wk[i * Dd + j] * wa;
    }
    g_wqa[i] = a;
    g_wka[i] = b;
    g_bvev[i] = bv[i] + bev[i];
    if (i < DE) {
        float c = 0.f;
        for (int j = 0; j < Dd; j++) c += Wew[i * Dd + j] * Wa[j];
        g_wewa[i] = c;
    }
    if (i == 0) {
        float cc = 0.f;
        for (int j = 0; j < Dd; j++) cc += (bq[j] + bk[j] + bew[j]) * Wa[j];
        g_cc = cc;
    }
}

// ---------------- K1: zero accumulators --------------------------------------
__global__ void k_zero() {
    int i = blockIdx.x * blockDim.x + threadIdx.x;
    if (i < NODES) { g_att_sum[i] = 0.f; g_counts[i] = 0; }
}

// ---------------- K2: fused x->fp16 convert + qa/ka dots (one x read) --------
__global__ void k_fusedx(const float* __restrict__ x) {
    int warp = (blockIdx.x * blockDim.x + threadIdx.x) >> 5;
    int lane = threadIdx.x & 31;
    if (warp >= NODES) return;
    float4 xv = *(const float4*)&x[(size_t)warp * Dd + lane * 4];
    // fp16 conversion + store (coalesced 8B/lane)
    __half2 h0 = __floats2half2_rn(xv.x, xv.y);
    __half2 h1 = __floats2half2_rn(xv.z, xv.w);
    uint2 packed;
    packed.x = *(uint32_t*)&h0;
    packed.y = *(uint32_t*)&h1;
    *(uint2*)&g_xh[(size_t)warp * Dd + lane * 4] = packed;
    // qa / ka dots
    float4 wq = *(const float4*)&g_wqa[lane * 4];
    float4 wk = *(const float4*)&g_wka[lane * 4];
    float a = xv.x * wq.x + xv.y * wq.y + xv.z * wq.z + xv.w * wq.w;
    float b = xv.x * wk.x + xv.y * wk.y + xv.z * wk.z + xv.w * wk.w;
    #pragma unroll
    for (int off = 16; off > 0; off >>= 1) {
        a += __shfl_xor_sync(0xffffffffu, a, off);
        b += __shfl_xor_sync(0xffffffffu, b, off);
    }
    if (lane == 0) g_qka[warp] = make_float2(a, b);
}

// ---------------- K3: src histogram ------------------------------------------
__global__ void k_count(const int* __restrict__ ei, const int* __restrict__ bi) {
    int e = blockIdx.x * blockDim.x + threadIdx.x;
    if (e >= Ee) return;
    atomicAdd(&g_counts[bi[e] * Nn + ei[e]], 1);
}

// ---------------- K4: single-block exclusive scan of counts ------------------
#define SCAN_T 1024
#define SCAN_CH 40
__global__ void k_scan() {
    __shared__ int sh[SCAN_T];
    int t = threadIdx.x;
    int start = t * SCAN_CH;
    int end = min(start + SCAN_CH, NODES);
    int s = 0;
    for (int i = start; i < end; i++) s += g_counts[i];
    sh[t] = s;
    __syncthreads();
    for (int off = 1; off < SCAN_T; off <<= 1) {
        int v = (t >= off) ? sh[t - off] : 0;
        __syncthreads();
        sh[t] += v;
        __syncthreads();
    }
    int run = (t == 0) ? 0 : sh[t - 1];
    for (int i = start; i < end; i++) {
        g_offsets[i] = run;
        g_cursor[i] = run;
        run += g_counts[i];
    }
    if (t == SCAN_T - 1) g_offsets[NODES] = sh[SCAN_T - 1];
}

// ---------------- K5: edge pass — coalesced dot, exp, seg-sum, sorted write --
// 8 lanes per edge for the e_emb dot (coalesced), then 1 edge/lane phase that
// computes exp(logit), accumulates att_sum, and writes the edge record
// DIRECTLY into src-sorted position (replaces the old separate scatter pass).
__global__ __launch_bounds__(256) void k_edge1(const int* __restrict__ ei,
                                               const float* __restrict__ e_emb,
                                               const int* __restrict__ bi) {
    __shared__ float ws4[DE];
    __shared__ float s_cc;
    __shared__ float sdot[8][32];
    int t = threadIdx.x;
    if (t < DE) ws4[t] = g_wewa[t];
    if (t == 0) s_cc = g_cc;
    __syncthreads();

    int wid  = t >> 5;
    int lane = t & 31;
    int base = (blockIdx.x * 8 + wid) * 32;      // 32 edges per warp

    // Phase B index loads issued early
    int e_mine = base + lane;
    int src = ei[e_mine];
    int dst = ei[Ee + e_mine];
    int b   = bi[e_mine];

    // Phase A: cooperative dot products (4 edges per LDG.128 span)
    int oct  = lane >> 3;
    int sub  = lane & 7;
    float w0 = ws4[sub * 4 + 0], w1 = ws4[sub * 4 + 1];
    float w2 = ws4[sub * 4 + 2], w3 = ws4[sub * 4 + 3];
    #pragma unroll
    for (int g = 0; g < 8; g++) {
        int e4 = base + g * 4 + oct;
        float4 v = *(const float4*)&e_emb[(size_t)e4 * DE + sub * 4];
        float d = v.x * w0 + v.y * w1 + v.z * w2 + v.w * w3;
        d += __shfl_xor_sync(0xffffffffu, d, 4);
        d += __shfl_xor_sync(0xffffffffu, d, 2);
        d += __shfl_xor_sync(0xffffffffu, d, 1);
        if (sub == 0) sdot[wid][g * 4 + oct] = d;
    }
    __syncwarp();

    // Phase B: one edge per lane
    float dot = sdot[wid][lane];
    int key  = b * Nn + src;
    int dstn = b * Nn + dst;
    float2 qs = g_qka[key];
    float2 kd = g_qka[dstn];
    float logit = (qs.x + kd.y + dot + s_cc) * RSQRT_DH;
    float ex = __expf(logit);
    atomicAdd(&g_att_sum[dstn], ex);
    int pos = atomicAdd(&g_cursor[key], 1);
    int4 pk;
    pk.x = e_mine;
    pk.y = dstn;
    pk.z = __float_as_int(ex);
    pk.w = 0;
    g_edge[pos] = pk;
}

// ---------------- K6: gather moments, one warp per src node ------------------
// Quad-batched fp16 x rows; alpha computed inline via __fdividef against the
// L2-resident att_sum table.
__global__ __launch_bounds__(128) void k_gather(const float* __restrict__ e_emb) {
    int s = blockIdx.x * 4 + (threadIdx.x >> 5);
    int lane = threadIdx.x & 31;
    if (s >= NODES) return;

    int start = g_offsets[s];
    int end   = g_offsets[s + 1];

    float4 accx = make_float4(0.f, 0.f, 0.f, 0.f);
    float4 acce = make_float4(0.f, 0.f, 0.f, 0.f);
    float  accA = 0.f;

    int i = start;
    for (; i + 4 <= end; i += 4) {
        int4 m0 = g_edge[i + 0];
        int4 m1 = g_edge[i + 1];
        int4 m2 = g_edge[i + 2];
        int4 m3 = g_edge[i + 3];
        uint2 r0 = *(const uint2*)&g_xh[(size_t)m0.y * Dd + lane * 4];
        uint2 r1 = *(const uint2*)&g_xh[(size_t)m1.y * Dd + lane * 4];
        uint2 r2 = *(const uint2*)&g_xh[(size_t)m2.y * Dd + lane * 4];
        uint2 r3 = *(const uint2*)&g_xh[(size_t)m3.y * Dd + lane * 4];
        float s0 = g_att_sum[m0.y], s1 = g_att_sum[m1.y];
        float s2 = g_att_sum[m2.y], s3 = g_att_sum[m3.y];
        float4 e0 = make_float4(0.f,0.f,0.f,0.f), e1 = e0, e2 = e0, e3 = e0;
        if (lane < 8) {
            e0 = *(const float4*)&e_emb[(size_t)m0.x * DE + lane * 4];
            e1 = *(const float4*)&e_emb[(size_t)m1.x * DE + lane * 4];
            e2 = *(const float4*)&e_emb[(size_t)m2.x * DE + lane * 4];
            e3 = *(const float4*)&e_emb[(size_t)m3.x * DE + lane * 4];
        }
        float a0 = __fdividef(__int_as_float(m0.z), s0 + 1e-9f);
        float a1 = __fdividef(__int_as_float(m1.z), s1 + 1e-9f);
        float a2 = __fdividef(__int_as_float(m2.z), s2 + 1e-9f);
        float a3 = __fdividef(__int_as_float(m3.z), s3 + 1e-9f);
        float4 v0 = h4tof4(r0), v1 = h4tof4(r1), v2 = h4tof4(r2), v3 = h4tof4(r3);
        accx.x += a0*v0.x + a1*v1.x + a2*v2.x + a3*v3.x;
        accx.y += a0*v0.y + a1*v1.y + a2*v2.y + a3*v3.y;
        accx.z += a0*v0.z + a1*v1.z + a2*v2.z + a3*v3.z;
        accx.w += a0*v0.w + a1*v1.w + a2*v2.w + a3*v3.w;
        acce.x += a0*e0.x + a1*e1.x + a2*e2.x + a3*e3.x;
        acce.y += a0*e0.y + a1*e1.y + a2*e2.y + a3*e3.y;
        acce.z += a0*e0.z + a1*e1.z + a2*e2.z + a3*e3.z;
        acce.w += a0*e0.w + a1*e1.w + a2*e2.w + a3*e3.w;
        accA += a0 + a1 + a2 + a3;
    }
    for (; i < end; i++) {
        int4 m = g_edge[i];
        float a = __fdividef(__int_as_float(m.z), g_att_sum[m.y] + 1e-9f);
        uint2 r = *(const uint2*)&g_xh[(size_t)m.y * Dd + lane * 4];
        float4 ev = make_float4(0.f, 0.f, 0.f, 0.f);
        if (lane < 8) ev = *(const float4*)&e_emb[(size_t)m.x * DE + lane * 4];
        float4 v = h4tof4(r);
        accx.x += a * v.x; accx.y += a * v.y;
        accx.z += a * v.z; accx.w += a * v.w;
        acce.x += a * ev.x; acce.y += a * ev.y;
        acce.z += a * ev.z; acce.w += a * ev.w;
        accA += a;
    }

    *(float4*)&g_Mx[(size_t)s * Dd + lane * 4] = accx;
    if (lane < 8) *(float4*)&g_Me[(size_t)s * DE + lane * 4] = acce;
    if (lane == 0) g_sA[s] = accA;
}

// ---------------- K7: fused epilogue GEMM  out = [Mx|Me]@[Wv;Wev] + sA⊗(bv+bev)
#define OB_M 128
#define OB_K 16
#define NTILES 10   // 8 tiles from Mx/Wv (K=128) + 2 tiles from Me/Wev (K=32)
__global__ __launch_bounds__(256) void k_out(const float* __restrict__ Wv,
                                             const float* __restrict__ Wev,
                                             float* __restrict__ out) {
    __shared__ float As[2][OB_M * OB_K];   // row-major [m][k]
    __shared__ float Bs[2][OB_K * Dd];     // [k][n]
    __shared__ float sA_sh[OB_M];
    __shared__ float bb_sh[Dd];

    int t  = threadIdx.x;
    int m0 = blockIdx.x * OB_M;
    if (t < OB_M) {
        sA_sh[t] = g_sA[m0 + t];   // padded array, rows >= NODES are zero
        bb_sh[t] = g_bvev[t];
    }

    auto issue = [&](int stage, int tile) {
        #pragma unroll
        for (int it = 0; it < 2; it++) {
            int q = t + it * 256;
            int m = q >> 2, kq = q & 3;
            const float* srcA = (tile < 8)
                ? &g_Mx[(size_t)(m0 + m) * Dd + tile * OB_K + kq * 4]
                : &g_Me[(size_t)(m0 + m) * DE + (tile - 8) * OB_K + kq * 4];
            cp16(&As[stage][m * OB_K + kq * 4], srcA);
            int k = q >> 5, c4 = q & 31;
            const float* srcB = (tile < 8)
                ? &Wv[(size_t)(tile * OB_K + k) * Dd + c4 * 4]
                : &Wev[(size_t)((tile - 8) * OB_K + k) * Dd + c4 * 4];
            cp16(&Bs[stage][k * Dd + c4 * 4], srcB);
        }
    };

    issue(0, 0);
    CP_COMMIT();

    float acc[8][8];
    #pragma unroll
    for (int i = 0; i < 8; i++)
        #pragma unroll
        for (int j = 0; j < 8; j++) acc[i][j] = 0.f;

    int tx = t & 15, ty = t >> 4;

    for (int tile = 0; tile < NTILES; tile++) {
        int cur = tile & 1, nxt = cur ^ 1;
        if (tile + 1 < NTILES) {
            issue(nxt, tile + 1);
            CP_COMMIT();
            CP_WAIT(1);
        } else {
            CP_WAIT(0);
        }
        __syncthreads();
        #pragma unroll
        for (int k = 0; k < OB_K; k++) {
            float xv[8];
            #pragma unroll
            for (int i = 0; i < 8; i++) xv[i] = As[cur][(ty * 8 + i) * OB_K + k];
            float4 w0 = *(float4*)&Bs[cur][k * Dd + tx * 8];
            float4 w1 = *(float4*)&Bs[cur][k * Dd + tx * 8 + 4];
            #pragma unroll
            for (int i = 0; i < 8; i++) {
                acc[i][0] += xv[i] * w0.x;
                acc[i][1] += xv[i] * w0.y;
                acc[i][2] += xv[i] * w0.z;
                acc[i][3] += xv[i] * w0.w;
                acc[i][4] += xv[i] * w1.x;
                acc[i][5] += xv[i] * w1.y;
                acc[i][6] += xv[i] * w1.z;
                acc[i][7] += xv[i] * w1.w;
            }
        }
        __syncthreads();
    }

    #pragma unroll
    for (int i = 0; i < 8; i++) {
        int r = m0 + ty * 8 + i;
        if (r < NODES) {
            float sa = sA_sh[ty * 8 + i];
            int c0 = tx * 8;
            float4 o0, o1;
            o0.x = acc[i][0] + sa * bb_sh[c0 + 0];
            o0.y = acc[i][1] + sa * bb_sh[c0 + 1];
            o0.z = acc[i][2] + sa * bb_sh[c0 + 2];
            o0.w = acc[i][3] + sa * bb_sh[c0 + 3];
            o1.x = acc[i][4] + sa * bb_sh[c0 + 4];
            o1.y = acc[i][5] + sa * bb_sh[c0 + 5];
            o1.z = acc[i][6] + sa * bb_sh[c0 + 6];
            o1.w = acc[i][7] + sa * bb_sh[c0 + 7];
            *(float4*)&out[(size_t)r * Dd + c0]     = o0;
            *(float4*)&out[(size_t)r * Dd + c0 + 4] = o1;
        }
    }
}

// ---------------- launch ------------------------------------------------------
extern "C" void kernel_launch(void* const* d_in, const int* in_sizes, int n_in,
                              void* d_out, int out_size) {
    const float* x     = (const float*)d_in[0];
    const int*   ei    = (const int*)  d_in[1];
    const float* e_emb = (const float*)d_in[2];
    const int*   bi    = (const int*)  d_in[3];
    const float* Wq    = (const float*)d_in[4];
    const float* bq    = (const float*)d_in[5];
    const float* Wk    = (const float*)d_in[6];
    const float* bk    = (const float*)d_in[7];
    const float* Wv    = (const float*)d_in[8];
    const float* bv    = (const float*)d_in[9];
    const float* Wew   = (const float*)d_in[10];
    const float* bew   = (const float*)d_in[11];
    const float* Wev   = (const float*)d_in[12];
    const float* bev   = (const float*)d_in[13];
    const float* Wa    = (const float*)d_in[14];
    float* out = (float*)d_out;

    k_prep<<<1, 128>>>(Wq, Wk, Wew, bq, bk, bew, Wa, bv, bev);
    k_zero<<<(NODES + 255) / 256, 256>>>();
    k_fusedx<<<(NODES + 7) / 8, 256>>>(x);
    k_count<<<(Ee + 255) / 256, 256>>>(ei, bi);
    k_scan<<<1, SCAN_T>>>();
    k_edge1<<<Ee / 256, 256>>>(ei, e_emb, bi);   // 640000 = 2500 * 256 exactly
    k_gather<<<(NODES + 3) / 4, 128>>>(e_emb);
    k_out<<<NODES_PAD / OB_M, 256>>>(Wv, Wev, out);
}

// round 10
// speedup vs baseline: 1.4128x; 1.0658x over previous
#include <cuda_runtime.h>
#include <cuda_fp16.h>
#include <math.h>
#include <stdint.h>

#define Bb 4
#define Nn 10000
#define Dd 128
#define DE 32
#define Ee 640000
#define NODES (Bb*Nn)            // 40000
#define NODES_PAD 40064          // 313 * 128
#define RSQRT_DH 0.17677669529663687f

// ---------------- scratch (device globals; zero-init, no allocation) ---------
__device__ float2 g_qka[NODES];          // {qa, ka} packed
__device__ float g_att_sum[NODES];
__device__ int   g_counts[NODES];
__device__ int   g_offsets[NODES + 1];
__device__ int   g_cursor[NODES];
__device__ int2  g_edge2[Ee];            // {dst_node, exp_bits} sorted by src
__device__ __half g_eh[(size_t)Ee * DE]; // fp16 e_emb rows in src-sorted order (41 MB)
__device__ __half g_xh[NODES * Dd];      // fp16 copy of x (10 MB, L2-resident)
__device__ float g_Mx[NODES_PAD * Dd];   // Σ alpha * x[dst]
__device__ float g_Me[NODES_PAD * DE];   // Σ alpha * e_emb[e]
__device__ float g_sA[NODES_PAD];        // Σ alpha
__device__ float g_wqa[Dd];
__device__ float g_wka[Dd];
__device__ float g_wewa[DE];
__device__ float g_bvev[Dd];             // bv + bev
__device__ float g_cc;                   // (bq+bk+bew)·Wa

// ---------------- cp.async helpers ------------------------------------------
__device__ __forceinline__ void cp16(void* dst, const void* src) {
    uint32_t d = (uint32_t)__cvta_generic_to_shared(dst);
    asm volatile("cp.async.cg.shared.global [%0], [%1], 16;" :: "r"(d), "l"(src));
}
#define CP_COMMIT() asm volatile("cp.async.commit_group;")
#define CP_WAIT(n)  asm volatile("cp.async.wait_group %0;" :: "n"(n))

__device__ __forceinline__ float4 h4tof4(uint2 r) {
    __half2* p = (__half2*)&r;
    float2 lo = __half22float2(p[0]);
    float2 hi = __half22float2(p[1]);
    return make_float4(lo.x, lo.y, hi.x, hi.y);
}

// ---------------- K0: fold Wa into projections; bias combos -----------------
__global__ void k_prep(const float* __restrict__ Wq, const float* __restrict__ Wk,
                       const float* __restrict__ Wew,
                       const float* __restrict__ bq, const float* __restrict__ bk,
                       const float* __restrict__ bew, const float* __restrict__ Wa,
                       const float* __restrict__ bv, const float* __restrict__ bev) {
    int i = threadIdx.x;  // 128 threads
    float a = 0.f, b = 0.f;
    for (int j = 0; j < Dd; j++) {
        float wa = Wa[j];
        a += Wq[i * Dd + j] * wa;
        b += Wk[i * Dd + j] * wa;
    }
    g_wqa[i] = a;
    g_wka[i] = b;
    g_bvev[i] = bv[i] + bev[i];
    if (i < DE) {
        float c = 0.f;
        for (int j = 0; j < Dd; j++) c += Wew[i * Dd + j] * Wa[j];
        g_wewa[i] = c;
    }
    if (i == 0) {
        float cc = 0.f;
        for (int j = 0; j < Dd; j++) cc += (bq[j] + bk[j] + bew[j]) * Wa[j];
        g_cc = cc;
    }
}

// ---------------- K1: zero accumulators --------------------------------------
__global__ void k_zero() {
    int i = blockIdx.x * blockDim.x + threadIdx.x;
    if (i < NODES) { g_att_sum[i] = 0.f; g_counts[i] = 0; }
}

// ---------------- K2: fused x->fp16 convert + qa/ka dots (one x read) --------
__global__ void k_fusedx(const float* __restrict__ x) {
    int warp = (blockIdx.x * blockDim.x + threadIdx.x) >> 5;
    int lane = threadIdx.x & 31;
    if (warp >= NODES) return;
    float4 xv = *(const float4*)&x[(size_t)warp * Dd + lane * 4];
    __half2 h0 = __floats2half2_rn(xv.x, xv.y);
    __half2 h1 = __floats2half2_rn(xv.z, xv.w);
    uint2 packed;
    packed.x = *(uint32_t*)&h0;
    packed.y = *(uint32_t*)&h1;
    *(uint2*)&g_xh[(size_t)warp * Dd + lane * 4] = packed;
    float4 wq = *(const float4*)&g_wqa[lane * 4];
    float4 wk = *(const float4*)&g_wka[lane * 4];
    float a = xv.x * wq.x + xv.y * wq.y + xv.z * wq.z + xv.w * wq.w;
    float b = xv.x * wk.x + xv.y * wk.y + xv.z * wk.z + xv.w * wk.w;
    #pragma unroll
    for (int off = 16; off > 0; off >>= 1) {
        a += __shfl_xor_sync(0xffffffffu, a, off);
        b += __shfl_xor_sync(0xffffffffu, b, off);
    }
    if (lane == 0) g_qka[warp] = make_float2(a, b);
}

// ---------------- K3: src histogram ------------------------------------------
__global__ void k_count(const int* __restrict__ ei, const int* __restrict__ bi) {
    int e = blockIdx.x * blockDim.x + threadIdx.x;
    if (e >= Ee) return;
    atomicAdd(&g_counts[bi[e] * Nn + ei[e]], 1);
}

// ---------------- K4: single-block exclusive scan of counts ------------------
#define SCAN_T 1024
#define SCAN_CH 40
__global__ void k_scan() {
    __shared__ int sh[SCAN_T];
    int t = threadIdx.x;
    int start = t * SCAN_CH;
    int end = min(start + SCAN_CH, NODES);
    int s = 0;
    for (int i = start; i < end; i++) s += g_counts[i];
    sh[t] = s;
    __syncthreads();
    for (int off = 1; off < SCAN_T; off <<= 1) {
        int v = (t >= off) ? sh[t - off] : 0;
        __syncthreads();
        sh[t] += v;
        __syncthreads();
    }
    int run = (t == 0) ? 0 : sh[t - 1];
    for (int i = start; i < end; i++) {
        g_offsets[i] = run;
        g_cursor[i] = run;
        run += g_counts[i];
    }
    if (t == SCAN_T - 1) g_offsets[NODES] = sh[SCAN_T - 1];
}

// ---------------- K5: edge pass — dot, exp, seg-sum, sorted record + fp16 row
// Phase A: coalesced cooperative e_emb dots (4 edges per LDG.128 span).
// Phase B: per-lane exp / att_sum atomic / sorted-position claim.
// Phase C: reload e_emb from L1 (block slice = 32KB, L1-resident) and write the
//          fp16 row into src-sorted g_eh so the gather never touches e_emb.
__global__ __launch_bounds__(256) void k_edge1(const int* __restrict__ ei,
                                               const float* __restrict__ e_emb,
                                               const int* __restrict__ bi) {
    __shared__ float ws4[DE];
    __shared__ float s_cc;
    __shared__ float sdot[8][32];
    int t = threadIdx.x;
    if (t < DE) ws4[t] = g_wewa[t];
    if (t == 0) s_cc = g_cc;
    __syncthreads();

    int wid  = t >> 5;
    int lane = t & 31;
    int base = (blockIdx.x * 8 + wid) * 32;      // 32 edges per warp

    // Phase B index loads issued early
    int e_mine = base + lane;
    int src = ei[e_mine];
    int dst = ei[Ee + e_mine];
    int b   = bi[e_mine];

    // Phase A: cooperative dot products
    int oct  = lane >> 3;
    int sub  = lane & 7;
    float w0 = ws4[sub * 4 + 0], w1 = ws4[sub * 4 + 1];
    float w2 = ws4[sub * 4 + 2], w3 = ws4[sub * 4 + 3];
    #pragma unroll
    for (int g = 0; g < 8; g++) {
        int e4 = base + g * 4 + oct;
        float4 v = *(const float4*)&e_emb[(size_t)e4 * DE + sub * 4];
        float d = v.x * w0 + v.y * w1 + v.z * w2 + v.w * w3;
        d += __shfl_xor_sync(0xffffffffu, d, 4);
        d += __shfl_xor_sync(0xffffffffu, d, 2);
        d += __shfl_xor_sync(0xffffffffu, d, 1);
        if (sub == 0) sdot[wid][g * 4 + oct] = d;
    }
    __syncwarp();

    // Phase B: one edge per lane
    float dot = sdot[wid][lane];
    int key  = b * Nn + src;
    int dstn = b * Nn + dst;
    float2 qs = g_qka[key];
    float2 kd = g_qka[dstn];
    float logit = (qs.x + kd.y + dot + s_cc) * RSQRT_DH;
    float ex = __expf(logit);
    atomicAdd(&g_att_sum[dstn], ex);
    int pos = atomicAdd(&g_cursor[key], 1);
    g_edge2[pos] = make_int2(dstn, __float_as_int(ex));

    // Phase C: fp16 e_emb row to sorted position (reloads hit L1)
    #pragma unroll
    for (int g = 0; g < 8; g++) {
        int j = g * 4 + oct;                     // edge index within warp
        int pj = __shfl_sync(0xffffffffu, pos, j);
        int e4 = base + j;
        float4 v = *(const float4*)&e_emb[(size_t)e4 * DE + sub * 4];
        __half2 h0 = __floats2half2_rn(v.x, v.y);
        __half2 h1 = __floats2half2_rn(v.z, v.w);
        uint2 packed;
        packed.x = *(uint32_t*)&h0;
        packed.y = *(uint32_t*)&h1;
        *(uint2*)&g_eh[(size_t)pj * DE + sub * 4] = packed;
    }
}

// ---------------- K6: gather moments, one warp per src node ------------------
// Records + fp16 e rows are position-indexed (sequential); only x rows and the
// 160KB att_sum table are random (both L2-resident). Every lane owns one of
// the 32 e-components -> no predication.
__global__ __launch_bounds__(128) void k_gather() {
    int s = blockIdx.x * 4 + (threadIdx.x >> 5);
    int lane = threadIdx.x & 31;
    if (s >= NODES) return;

    int start = g_offsets[s];
    int end   = g_offsets[s + 1];

    float4 accx = make_float4(0.f, 0.f, 0.f, 0.f);
    float acce = 0.f;
    float accA = 0.f;

    int i = start;
    for (; i + 4 <= end; i += 4) {
        int2 m0 = g_edge2[i + 0];
        int2 m1 = g_edge2[i + 1];
        int2 m2 = g_edge2[i + 2];
        int2 m3 = g_edge2[i + 3];
        // sequential fp16 e rows, independent of record loads
        float h0 = __half2float(g_eh[(size_t)(i + 0) * DE + lane]);
        float h1 = __half2float(g_eh[(size_t)(i + 1) * DE + lane]);
        float h2 = __half2float(g_eh[(size_t)(i + 2) * DE + lane]);
        float h3 = __half2float(g_eh[(size_t)(i + 3) * DE + lane]);
        uint2 r0 = *(const uint2*)&g_xh[(size_t)m0.x * Dd + lane * 4];
        uint2 r1 = *(const uint2*)&g_xh[(size_t)m1.x * Dd + lane * 4];
        uint2 r2 = *(const uint2*)&g_xh[(size_t)m2.x * Dd + lane * 4];
        uint2 r3 = *(const uint2*)&g_xh[(size_t)m3.x * Dd + lane * 4];
        float s0 = g_att_sum[m0.x], s1 = g_att_sum[m1.x];
        float s2 = g_att_sum[m2.x], s3 = g_att_sum[m3.x];
        float a0 = __fdividef(__int_as_float(m0.y), s0 + 1e-9f);
        float a1 = __fdividef(__int_as_float(m1.y), s1 + 1e-9f);
        float a2 = __fdividef(__int_as_float(m2.y), s2 + 1e-9f);
        float a3 = __fdividef(__int_as_float(m3.y), s3 + 1e-9f);
        float4 v0 = h4tof4(r0), v1 = h4tof4(r1), v2 = h4tof4(r2), v3 = h4tof4(r3);
        accx.x += a0*v0.x + a1*v1.x + a2*v2.x + a3*v3.x;
        accx.y += a0*v0.y + a1*v1.y + a2*v2.y + a3*v3.y;
        accx.z += a0*v0.z + a1*v1.z + a2*v2.z + a3*v3.z;
        accx.w += a0*v0.w + a1*v1.w + a2*v2.w + a3*v3.w;
        acce += a0*h0 + a1*h1 + a2*h2 + a3*h3;
        accA += a0 + a1 + a2 + a3;
    }
    for (; i < end; i++) {
        int2 m = g_edge2[i];
        float h = __half2float(g_eh[(size_t)i * DE + lane]);
        uint2 r = *(const uint2*)&g_xh[(size_t)m.x * Dd + lane * 4];
        float a = __fdividef(__int_as_float(m.y), g_att_sum[m.x] + 1e-9f);
        float4 v = h4tof4(r);
        accx.x += a * v.x; accx.y += a * v.y;
        accx.z += a * v.z; accx.w += a * v.w;
        acce += a * h;
        accA += a;
    }

    *(float4*)&g_Mx[(size_t)s * Dd + lane * 4] = accx;
    g_Me[(size_t)s * DE + lane] = acce;          // full-warp coalesced
    if (lane == 0) g_sA[s] = accA;
}

// ---------------- K7: fused epilogue GEMM  out = [Mx|Me]@[Wv;Wev] + sA⊗(bv+bev)
#define OB_M 128
#define OB_K 16
#define NTILES 10   // 8 tiles from Mx/Wv (K=128) + 2 tiles from Me/Wev (K=32)
__global__ __launch_bounds__(256) void k_out(const float* __restrict__ Wv,
                                             const float* __restrict__ Wev,
                                             float* __restrict__ out) {
    __shared__ float As[2][OB_M * OB_K];   // row-major [m][k]
    __shared__ float Bs[2][OB_K * Dd];     // [k][n]
    __shared__ float sA_sh[OB_M];
    __shared__ float bb_sh[Dd];

    int t  = threadIdx.x;
    int m0 = blockIdx.x * OB_M;
    if (t < OB_M) {
        sA_sh[t] = g_sA[m0 + t];   // padded array, rows >= NODES are zero
        bb_sh[t] = g_bvev[t];
    }

    auto issue = [&](int stage, int tile) {
        #pragma unroll
        for (int it = 0; it < 2; it++) {
            int q = t + it * 256;
            int m = q >> 2, kq = q & 3;
            const float* srcA = (tile < 8)
                ? &g_Mx[(size_t)(m0 + m) * Dd + tile * OB_K + kq * 4]
                : &g_Me[(size_t)(m0 + m) * DE + (tile - 8) * OB_K + kq * 4];
            cp16(&As[stage][m * OB_K + kq * 4], srcA);
            int k = q >> 5, c4 = q & 31;
            const float* srcB = (tile < 8)
                ? &Wv[(size_t)(tile * OB_K + k) * Dd + c4 * 4]
                : &Wev[(size_t)((tile - 8) * OB_K + k) * Dd + c4 * 4];
            cp16(&Bs[stage][k * Dd + c4 * 4], srcB);
        }
    };

    issue(0, 0);
    CP_COMMIT();

    float acc[8][8];
    #pragma unroll
    for (int i = 0; i < 8; i++)
        #pragma unroll
        for (int j = 0; j < 8; j++) acc[i][j] = 0.f;

    int tx = t & 15, ty = t >> 4;

    for (int tile = 0; tile < NTILES; tile++) {
        int cur = tile & 1, nxt = cur ^ 1;
        if (tile + 1 < NTILES) {
            issue(nxt, tile + 1);
            CP_COMMIT();
            CP_WAIT(1);
        } else {
            CP_WAIT(0);
        }
        __syncthreads();
        #pragma unroll
        for (int k = 0; k < OB_K; k++) {
            float xv[8];
            #pragma unroll
            for (int i = 0; i < 8; i++) xv[i] = As[cur][(ty * 8 + i) * OB_K + k];
            float4 w0 = *(float4*)&Bs[cur][k * Dd + tx * 8];
            float4 w1 = *(float4*)&Bs[cur][k * Dd + tx * 8 + 4];
            #pragma unroll
            for (int i = 0; i < 8; i++) {
                acc[i][0] += xv[i] * w0.x;
                acc[i][1] += xv[i] * w0.y;
                acc[i][2] += xv[i] * w0.z;
                acc[i][3] += xv[i] * w0.w;
                acc[i][4] += xv[i] * w1.x;
                acc[i][5] += xv[i] * w1.y;
                acc[i][6] += xv[i] * w1.z;
                acc[i][7] += xv[i] * w1.w;
            }
        }
        __syncthreads();
    }

    #pragma unroll
    for (int i = 0; i < 8; i++) {
        int r = m0 + ty * 8 + i;
        if (r < NODES) {
            float sa = sA_sh[ty * 8 + i];
            int c0 = tx * 8;
            float4 o0, o1;
            o0.x = acc[i][0] + sa * bb_sh[c0 + 0];
            o0.y = acc[i][1] + sa * bb_sh[c0 + 1];
            o0.z = acc[i][2] + sa * bb_sh[c0 + 2];
            o0.w = acc[i][3] + sa * bb_sh[c0 + 3];
            o1.x = acc[i][4] + sa * bb_sh[c0 + 4];
            o1.y = acc[i][5] + sa * bb_sh[c0 + 5];
            o1.z = acc[i][6] + sa * bb_sh[c0 + 6];
            o1.w = acc[i][7] + sa * bb_sh[c0 + 7];
            *(float4*)&out[(size_t)r * Dd + c0]     = o0;
            *(float4*)&out[(size_t)r * Dd + c0 + 4] = o1;
        }
    }
}

// ---------------- launch ------------------------------------------------------
extern "C" void kernel_launch(void* const* d_in, const int* in_sizes, int n_in,
                              void* d_out, int out_size) {
    const float* x     = (const float*)d_in[0];
    const int*   ei    = (const int*)  d_in[1];
    const float* e_emb = (const float*)d_in[2];
    const int*   bi    = (const int*)  d_in[3];
    const float* Wq    = (const float*)d_in[4];
    const float* bq    = (const float*)d_in[5];
    const float* Wk    = (const float*)d_in[6];
    const float* bk    = (const float*)d_in[7];
    const float* Wv    = (const float*)d_in[8];
    const float* bv    = (const float*)d_in[9];
    const float* Wew   = (const float*)d_in[10];
    const float* bew   = (const float*)d_in[11];
    const float* Wev   = (const float*)d_in[12];
    const float* bev   = (const float*)d_in[13];
    const float* Wa    = (const float*)d_in[14];
    float* out = (float*)d_out;

    k_prep<<<1, 128>>>(Wq, Wk, Wew, bq, bk, bew, Wa, bv, bev);
    k_zero<<<(NODES + 255) / 256, 256>>>();
    k_fusedx<<<(NODES + 7) / 8, 256>>>(x);
    k_count<<<(Ee + 255) / 256, 256>>>(ei, bi);
    k_scan<<<1, SCAN_T>>>();
    k_edge1<<<Ee / 256, 256>>>(ei, e_emb, bi);   // 640000 = 2500 * 256 exactly
    k_gather<<<(NODES + 3) / 4, 128>>>();
    k_out<<<NODES_PAD / OB_M, 256>>>(Wv, Wev, out);
}

// round 11
// speedup vs baseline: 1.5602x; 1.1043x over previous
#include <cuda_runtime.h>
#include <cuda_fp16.h>
#include <math.h>
#include <stdint.h>

#define Bb 4
#define Nn 10000
#define Dd 128
#define DE 32
#define Ee 640000
#define NODES (Bb*Nn)            // 40000
#define NODES_PAD 40064          // 313 * 128
#define RSQRT_DH 0.17677669529663687f

// ---------------- scratch (device globals; zero-init, no allocation) ---------
__device__ float2 g_qka[NODES];          // {qa, ka} packed
__device__ float g_att_sum[NODES];
__device__ int   g_counts[NODES];
__device__ int   g_offsets[NODES + 1];
__device__ int   g_cursor[NODES];
__device__ int2  g_edge2[Ee];            // {dst_node, exp_bits} sorted by src
__device__ __half g_eh[(size_t)Ee * DE]; // fp16 e_emb rows in src-sorted order (41 MB)
__device__ __half g_xh[NODES * Dd];      // fp16 copy of x (10 MB, L2-resident)
__device__ float g_Mx[NODES_PAD * Dd];   // Σ alpha * x[dst]
__device__ float g_Me[NODES_PAD * DE];   // Σ alpha * e_emb[e]
__device__ float g_sA[NODES_PAD];        // Σ alpha
__device__ float g_wqa[Dd];
__device__ float g_wka[Dd];
__device__ float g_wewa[DE];
__device__ float g_bvev[Dd];             // bv + bev
__device__ float g_cc;                   // (bq+bk+bew)·Wa

// ---------------- cp.async helpers ------------------------------------------
__device__ __forceinline__ void cp16(void* dst, const void* src) {
    uint32_t d = (uint32_t)__cvta_generic_to_shared(dst);
    asm volatile("cp.async.cg.shared.global [%0], [%1], 16;" :: "r"(d), "l"(src));
}
#define CP_COMMIT() asm volatile("cp.async.commit_group;")
#define CP_WAIT(n)  asm volatile("cp.async.wait_group %0;" :: "n"(n))

__device__ __forceinline__ float4 h4tof4(uint2 r) {
    __half2* p = (__half2*)&r;
    float2 lo = __half22float2(p[0]);
    float2 hi = __half22float2(p[1]);
    return make_float4(lo.x, lo.y, hi.x, hi.y);
}

// ---------------- K0: fold Wa into projections (warp per output row) ---------
__global__ void k_prep(const float* __restrict__ Wq, const float* __restrict__ Wk,
                       const float* __restrict__ Wew,
                       const float* __restrict__ bq, const float* __restrict__ bk,
                       const float* __restrict__ bew, const float* __restrict__ Wa,
                       const float* __restrict__ bv, const float* __restrict__ bev) {
    int w    = (blockIdx.x * blockDim.x + threadIdx.x) >> 5;  // 0..127
    int lane = threadIdx.x & 31;
    if (w >= Dd) return;
    float a = 0.f, b = 0.f, c = 0.f, cc = 0.f;
    #pragma unroll
    for (int j = lane; j < Dd; j += 32) {
        float wa = Wa[j];
        a += Wq[w * Dd + j] * wa;
        b += Wk[w * Dd + j] * wa;
        if (w < DE) c += Wew[w * Dd + j] * wa;
        if (w == 0) cc += (bq[j] + bk[j] + bew[j]) * wa;
    }
    #pragma unroll
    for (int off = 16; off > 0; off >>= 1) {
        a  += __shfl_xor_sync(0xffffffffu, a, off);
        b  += __shfl_xor_sync(0xffffffffu, b, off);
        c  += __shfl_xor_sync(0xffffffffu, c, off);
        cc += __shfl_xor_sync(0xffffffffu, cc, off);
    }
    if (lane == 0) {
        g_wqa[w] = a;
        g_wka[w] = b;
        g_bvev[w] = bv[w] + bev[w];
        if (w < DE) g_wewa[w] = c;
        if (w == 0) g_cc = cc;
    }
}

// ---------------- K1: zero accumulators --------------------------------------
__global__ void k_zero() {
    int i = blockIdx.x * blockDim.x + threadIdx.x;
    if (i < NODES) { g_att_sum[i] = 0.f; g_counts[i] = 0; }
}

// ---------------- K2: fused x->fp16 convert + qa/ka dots (one x read) --------
__global__ void k_fusedx(const float* __restrict__ x) {
    int warp = (blockIdx.x * blockDim.x + threadIdx.x) >> 5;
    int lane = threadIdx.x & 31;
    if (warp >= NODES) return;
    float4 xv = *(const float4*)&x[(size_t)warp * Dd + lane * 4];
    __half2 h0 = __floats2half2_rn(xv.x, xv.y);
    __half2 h1 = __floats2half2_rn(xv.z, xv.w);
    uint2 packed;
    packed.x = *(uint32_t*)&h0;
    packed.y = *(uint32_t*)&h1;
    *(uint2*)&g_xh[(size_t)warp * Dd + lane * 4] = packed;
    float4 wq = *(const float4*)&g_wqa[lane * 4];
    float4 wk = *(const float4*)&g_wka[lane * 4];
    float a = xv.x * wq.x + xv.y * wq.y + xv.z * wq.z + xv.w * wq.w;
    float b = xv.x * wk.x + xv.y * wk.y + xv.z * wk.z + xv.w * wk.w;
    #pragma unroll
    for (int off = 16; off > 0; off >>= 1) {
        a += __shfl_xor_sync(0xffffffffu, a, off);
        b += __shfl_xor_sync(0xffffffffu, b, off);
    }
    if (lane == 0) g_qka[warp] = make_float2(a, b);
}

// ---------------- K3: src histogram, 4 edges/thread via int4 -----------------
__global__ void k_count(const int* __restrict__ ei, const int* __restrict__ bi) {
    int q = blockIdx.x * blockDim.x + threadIdx.x;   // quad index
    if (q >= Ee / 4) return;
    int4 s4 = ((const int4*)ei)[q];
    int4 b4 = ((const int4*)bi)[q];
    atomicAdd(&g_counts[b4.x * Nn + s4.x], 1);
    atomicAdd(&g_counts[b4.y * Nn + s4.y], 1);
    atomicAdd(&g_counts[b4.z * Nn + s4.z], 1);
    atomicAdd(&g_counts[b4.w * Nn + s4.w], 1);
}

// ---------------- K4: single-block exclusive scan of counts ------------------
#define SCAN_T 1024
#define SCAN_CH 40
__global__ void k_scan() {
    __shared__ int sh[SCAN_T];
    int t = threadIdx.x;
    int start = t * SCAN_CH;
    int end = min(start + SCAN_CH, NODES);
    int s = 0;
    for (int i = start; i < end; i++) s += g_counts[i];
    sh[t] = s;
    __syncthreads();
    for (int off = 1; off < SCAN_T; off <<= 1) {
        int v = (t >= off) ? sh[t - off] : 0;
        __syncthreads();
        sh[t] += v;
        __syncthreads();
    }
    int run = (t == 0) ? 0 : sh[t - 1];
    for (int i = start; i < end; i++) {
        g_offsets[i] = run;
        g_cursor[i] = run;
        run += g_counts[i];
    }
    if (t == SCAN_T - 1) g_offsets[NODES] = sh[SCAN_T - 1];
}

// ---------------- K5: edge pass — dot, exp, seg-sum, sorted record + fp16 row
__global__ __launch_bounds__(256) void k_edge1(const int* __restrict__ ei,
                                               const float* __restrict__ e_emb,
                                               const int* __restrict__ bi) {
    __shared__ float ws4[DE];
    __shared__ float s_cc;
    __shared__ float sdot[8][32];
    int t = threadIdx.x;
    if (t < DE) ws4[t] = g_wewa[t];
    if (t == 0) s_cc = g_cc;
    __syncthreads();

    int wid  = t >> 5;
    int lane = t & 31;
    int base = (blockIdx.x * 8 + wid) * 32;      // 32 edges per warp

    // Phase B index loads issued early
    int e_mine = base + lane;
    int src = ei[e_mine];
    int dst = ei[Ee + e_mine];
    int b   = bi[e_mine];

    // Phase A: cooperative dot products (4 edges per LDG.128 span)
    int oct  = lane >> 3;
    int sub  = lane & 7;
    float w0 = ws4[sub * 4 + 0], w1 = ws4[sub * 4 + 1];
    float w2 = ws4[sub * 4 + 2], w3 = ws4[sub * 4 + 3];
    #pragma unroll
    for (int g = 0; g < 8; g++) {
        int e4 = base + g * 4 + oct;
        float4 v = *(const float4*)&e_emb[(size_t)e4 * DE + sub * 4];
        float d = v.x * w0 + v.y * w1 + v.z * w2 + v.w * w3;
        d += __shfl_xor_sync(0xffffffffu, d, 4);
        d += __shfl_xor_sync(0xffffffffu, d, 2);
        d += __shfl_xor_sync(0xffffffffu, d, 1);
        if (sub == 0) sdot[wid][g * 4 + oct] = d;
    }
    __syncwarp();

    // Phase B: one edge per lane
    float dot = sdot[wid][lane];
    int key  = b * Nn + src;
    int dstn = b * Nn + dst;
    float2 qs = g_qka[key];
    float2 kd = g_qka[dstn];
    float logit = (qs.x + kd.y + dot + s_cc) * RSQRT_DH;
    float ex = __expf(logit);
    atomicAdd(&g_att_sum[dstn], ex);
    int pos = atomicAdd(&g_cursor[key], 1);
    g_edge2[pos] = make_int2(dstn, __float_as_int(ex));

    // Phase C: fp16 e_emb row to sorted position (reloads hit L1)
    #pragma unroll
    for (int g = 0; g < 8; g++) {
        int j = g * 4 + oct;                     // edge index within warp
        int pj = __shfl_sync(0xffffffffu, pos, j);
        int e4 = base + j;
        float4 v = *(const float4*)&e_emb[(size_t)e4 * DE + sub * 4];
        __half2 h0 = __floats2half2_rn(v.x, v.y);
        __half2 h1 = __floats2half2_rn(v.z, v.w);
        uint2 packed;
        packed.x = *(uint32_t*)&h0;
        packed.y = *(uint32_t*)&h1;
        *(uint2*)&g_eh[(size_t)pj * DE + sub * 4] = packed;
    }
}

// ---------------- K6: gather moments, one warp per src node (8-wide batch) ---
__global__ __launch_bounds__(128) void k_gather() {
    int s = blockIdx.x * 4 + (threadIdx.x >> 5);
    int lane = threadIdx.x & 31;
    if (s >= NODES) return;

    int start = g_offsets[s];
    int end   = g_offsets[s + 1];

    float4 accx = make_float4(0.f, 0.f, 0.f, 0.f);
    float acce = 0.f;
    float accA = 0.f;

    int i = start;
    for (; i + 8 <= end; i += 8) {
        int2 m[8];
        #pragma unroll
        for (int k = 0; k < 8; k++) m[k] = g_edge2[i + k];
        uint2 r[8];
        #pragma unroll
        for (int k = 0; k < 8; k++)
            r[k] = *(const uint2*)&g_xh[(size_t)m[k].x * Dd + lane * 4];
        float h[8];
        #pragma unroll
        for (int k = 0; k < 8; k++)
            h[k] = __half2float(g_eh[(size_t)(i + k) * DE + lane]);
        float sm[8];
        #pragma unroll
        for (int k = 0; k < 8; k++) sm[k] = g_att_sum[m[k].x];
        #pragma unroll
        for (int k = 0; k < 8; k++) {
            float a = __fdividef(__int_as_float(m[k].y), sm[k] + 1e-9f);
            float4 v = h4tof4(r[k]);
            accx.x += a * v.x; accx.y += a * v.y;
            accx.z += a * v.z; accx.w += a * v.w;
            acce += a * h[k];
            accA += a;
        }
    }
    for (; i < end; i++) {
        int2 m = g_edge2[i];
        float h = __half2float(g_eh[(size_t)i * DE + lane]);
        uint2 r = *(const uint2*)&g_xh[(size_t)m.x * Dd + lane * 4];
        float a = __fdividef(__int_as_float(m.y), g_att_sum[m.x] + 1e-9f);
        float4 v = h4tof4(r);
        accx.x += a * v.x; accx.y += a * v.y;
        accx.z += a * v.z; accx.w += a * v.w;
        acce += a * h;
        accA += a;
    }

    *(float4*)&g_Mx[(size_t)s * Dd + lane * 4] = accx;
    g_Me[(size_t)s * DE + lane] = acce;          // full-warp coalesced
    if (lane == 0) g_sA[s] = accA;
}

// ---------------- K7: fused epilogue GEMM  out = [Mx|Me]@[Wv;Wev] + sA⊗(bv+bev)
#define OB_M 128
#define OB_K 16
#define NTILES 10   // 8 tiles from Mx/Wv (K=128) + 2 tiles from Me/Wev (K=32)
__global__ __launch_bounds__(256) void k_out(const float* __restrict__ Wv,
                                             const float* __restrict__ Wev,
                                             float* __restrict__ out) {
    __shared__ float As[2][OB_M * OB_K];   // row-major [m][k]
    __shared__ float Bs[2][OB_K * Dd];     // [k][n]
    __shared__ float sA_sh[OB_M];
    __shared__ float bb_sh[Dd];

    int t  = threadIdx.x;
    int m0 = blockIdx.x * OB_M;
    if (t < OB_M) {
        sA_sh[t] = g_sA[m0 + t];   // padded array, rows >= NODES are zero
        bb_sh[t] = g_bvev[t];
    }

    auto issue = [&](int stage, int tile) {
        #pragma unroll
        for (int it = 0; it < 2; it++) {
            int q = t + it * 256;
            int m = q >> 2, kq = q & 3;
            const float* srcA = (tile < 8)
                ? &g_Mx[(size_t)(m0 + m) * Dd + tile * OB_K + kq * 4]
                : &g_Me[(size_t)(m0 + m) * DE + (tile - 8) * OB_K + kq * 4];
            cp16(&As[stage][m * OB_K + kq * 4], srcA);
            int k = q >> 5, c4 = q & 31;
            const float* srcB = (tile < 8)
                ? &Wv[(size_t)(tile * OB_K + k) * Dd + c4 * 4]
                : &Wev[(size_t)((tile - 8) * OB_K + k) * Dd + c4 * 4];
            cp16(&Bs[stage][k * Dd + c4 * 4], srcB);
        }
    };

    issue(0, 0);
    CP_COMMIT();

    float acc[8][8];
    #pragma unroll
    for (int i = 0; i < 8; i++)
        #pragma unroll
        for (int j = 0; j < 8; j++) acc[i][j] = 0.f;

    int tx = t & 15, ty = t >> 4;

    for (int tile = 0; tile < NTILES; tile++) {
        int cur = tile & 1, nxt = cur ^ 1;
        if (tile + 1 < NTILES) {
            issue(nxt, tile + 1);
            CP_COMMIT();
            CP_WAIT(1);
        } else {
            CP_WAIT(0);
        }
        __syncthreads();
        #pragma unroll
        for (int k = 0; k < OB_K; k++) {
            float xv[8];
            #pragma unroll
            for (int i = 0; i < 8; i++) xv[i] = As[cur][(ty * 8 + i) * OB_K + k];
            float4 w0 = *(float4*)&Bs[cur][k * Dd + tx * 8];
            float4 w1 = *(float4*)&Bs[cur][k * Dd + tx * 8 + 4];
            #pragma unroll
            for (int i = 0; i < 8; i++) {
                acc[i][0] += xv[i] * w0.x;
                acc[i][1] += xv[i] * w0.y;
                acc[i][2] += xv[i] * w0.z;
                acc[i][3] += xv[i] * w0.w;
                acc[i][4] += xv[i] * w1.x;
                acc[i][5] += xv[i] * w1.y;
                acc[i][6] += xv[i] * w1.z;
                acc[i][7] += xv[i] * w1.w;
            }
        }
        __syncthreads();
    }

    #pragma unroll
    for (int i = 0; i < 8; i++) {
        int r = m0 + ty * 8 + i;
        if (r < NODES) {
            float sa = sA_sh[ty * 8 + i];
            int c0 = tx * 8;
            float4 o0, o1;
            o0.x = acc[i][0] + sa * bb_sh[c0 + 0];
            o0.y = acc[i][1] + sa * bb_sh[c0 + 1];
            o0.z = acc[i][2] + sa * bb_sh[c0 + 2];
            o0.w = acc[i][3] + sa * bb_sh[c0 + 3];
            o1.x = acc[i][4] + sa * bb_sh[c0 + 4];
            o1.y = acc[i][5] + sa * bb_sh[c0 + 5];
            o1.z = acc[i][6] + sa * bb_sh[c0 + 6];
            o1.w = acc[i][7] + sa * bb_sh[c0 + 7];
            *(float4*)&out[(size_t)r * Dd + c0]     = o0;
            *(float4*)&out[(size_t)r * Dd + c0 + 4] = o1;
        }
    }
}

// ---------------- launch ------------------------------------------------------
extern "C" void kernel_launch(void* const* d_in, const int* in_sizes, int n_in,
                              void* d_out, int out_size) {
    const float* x     = (const float*)d_in[0];
    const int*   ei    = (const int*)  d_in[1];
    const float* e_emb = (const float*)d_in[2];
    const int*   bi    = (const int*)  d_in[3];
    const float* Wq    = (const float*)d_in[4];
    const float* bq    = (const float*)d_in[5];
    const float* Wk    = (const float*)d_in[6];
    const float* bk    = (const float*)d_in[7];
    const float* Wv    = (const float*)d_in[8];
    const float* bv    = (const float*)d_in[9];
    const float* Wew   = (const float*)d_in[10];
    const float* bew   = (const float*)d_in[11];
    const float* Wev   = (const float*)d_in[12];
    const float* bev   = (const float*)d_in[13];
    const float* Wa    = (const float*)d_in[14];
    float* out = (float*)d_out;

    k_prep<<<16, 256>>>(Wq, Wk, Wew, bq, bk, bew, Wa, bv, bev);
    k_zero<<<(NODES + 255) / 256, 256>>>();
    k_fusedx<<<(NODES + 7) / 8, 256>>>(x);
    k_count<<<(Ee / 4 + 255) / 256, 256>>>(ei, bi);
    k_scan<<<1, SCAN_T>>>();
    k_edge1<<<Ee / 256, 256>>>(ei, e_emb, bi);   // 640000 = 2500 * 256 exactly
    k_gather<<<(NODES + 3) / 4, 128>>>();
    k_out<<<NODES_PAD / OB_M, 256>>>(Wv, Wev, out);
}

// round 12
// speedup vs baseline: 1.8626x; 1.1938x over previous
#include <cuda_runtime.h>
#include <cuda_fp16.h>
#include <math.h>
#include <stdint.h>

#define Bb 4
#define Nn 10000
#define Dd 128
#define DE 32
#define Ee 640000
#define NODES (Bb*Nn)            // 40000
#define NODES_PAD 40064          // 313 * 128
#define RSQRT_DH 0.17677669529663687f

// ---------------- scratch (device globals; zero-init, no allocation) ---------
__device__ float2 g_qka[NODES];          // {qa, ka} packed
__device__ float g_att_sum[NODES];
__device__ int   g_counts[NODES];
__device__ int   g_offsets[NODES + 1];
__device__ int   g_cursor[NODES];
__device__ int2  g_edge2[Ee];            // {dst_node, exp_bits} sorted by src
__device__ __half g_eh[(size_t)Ee * DE]; // fp16 e_emb rows in src-sorted order (41 MB)
__device__ __half g_xh[NODES * Dd];      // fp16 copy of x (10 MB, L2-resident)
__device__ float g_Mx[NODES_PAD * Dd];   // Σ alpha * x[dst]
__device__ float g_Me[NODES_PAD * DE];   // Σ alpha * e_emb[e]
__device__ float g_sA[NODES_PAD];        // Σ alpha
__device__ float g_wqa[Dd];
__device__ float g_wka[Dd];
__device__ float g_wewa[DE];
__device__ float g_bvev[Dd];             // bv + bev
__device__ float g_cc;                   // (bq+bk+bew)·Wa

// ---------------- helpers -----------------------------------------------------
__device__ __forceinline__ void cp16(void* dst, const void* src) {
    uint32_t d = (uint32_t)__cvta_generic_to_shared(dst);
    asm volatile("cp.async.cg.shared.global [%0], [%1], 16;" :: "r"(d), "l"(src));
}
#define CP_COMMIT() asm volatile("cp.async.commit_group;")
#define CP_WAIT(n)  asm volatile("cp.async.wait_group %0;" :: "n"(n))

__device__ __forceinline__ float4 h4tof4(uint2 r) {
    __half2* p = (__half2*)&r;
    float2 lo = __half22float2(p[0]);
    float2 hi = __half22float2(p[1]);
    return make_float4(lo.x, lo.y, hi.x, hi.y);
}

__device__ __forceinline__ uint32_t f2tf32(float f) {
    uint32_t u;
    asm("cvt.rna.tf32.f32 %0, %1;" : "=r"(u) : "f"(f));
    return u;
}

__device__ __forceinline__ void mma_tf32(float* d, const uint32_t* a,
                                         uint32_t b0, uint32_t b1) {
    asm volatile(
        "mma.sync.aligned.m16n8k8.row.col.f32.tf32.tf32.f32 "
        "{%0,%1,%2,%3},{%4,%5,%6,%7},{%8,%9},{%0,%1,%2,%3};"
        : "+f"(d[0]), "+f"(d[1]), "+f"(d[2]), "+f"(d[3])
        : "r"(a[0]), "r"(a[1]), "r"(a[2]), "r"(a[3]), "r"(b0), "r"(b1));
}

// ---------------- K0: fused zero + prep (heterogeneous grid) -----------------
#define ZERO_BLKS 157   // ceil(40000/256)
__global__ void k_init(const float* __restrict__ Wq, const float* __restrict__ Wk,
                       const float* __restrict__ Wew,
                       const float* __restrict__ bq, const float* __restrict__ bk,
                       const float* __restrict__ bew, const float* __restrict__ Wa,
                       const float* __restrict__ bv, const float* __restrict__ bev) {
    if (blockIdx.x < ZERO_BLKS) {
        int i = blockIdx.x * 256 + threadIdx.x;
        if (i < NODES) { g_att_sum[i] = 0.f; g_counts[i] = 0; }
        return;
    }
    int w    = ((blockIdx.x - ZERO_BLKS) * 256 + threadIdx.x) >> 5;  // 0..127
    int lane = threadIdx.x & 31;
    if (w >= Dd) return;
    float a = 0.f, b = 0.f, c = 0.f, cc = 0.f;
    #pragma unroll
    for (int j = lane; j < Dd; j += 32) {
        float wa = Wa[j];
        a += Wq[w * Dd + j] * wa;
        b += Wk[w * Dd + j] * wa;
        if (w < DE) c += Wew[w * Dd + j] * wa;
        if (w == 0) cc += (bq[j] + bk[j] + bew[j]) * wa;
    }
    #pragma unroll
    for (int off = 16; off > 0; off >>= 1) {
        a  += __shfl_xor_sync(0xffffffffu, a, off);
        b  += __shfl_xor_sync(0xffffffffu, b, off);
        c  += __shfl_xor_sync(0xffffffffu, c, off);
        cc += __shfl_xor_sync(0xffffffffu, cc, off);
    }
    if (lane == 0) {
        g_wqa[w] = a;
        g_wka[w] = b;
        g_bvev[w] = bv[w] + bev[w];
        if (w < DE) g_wewa[w] = c;
        if (w == 0) g_cc = cc;
    }
}

// ---------------- K1: fused (x->fp16 + qa/ka) ∥ src histogram ----------------
#define FX_BLKS 5000   // NODES / 8 warps-per-block
__global__ void k_fxc(const float* __restrict__ x, const int* __restrict__ ei,
                      const int* __restrict__ bi) {
    if (blockIdx.x < FX_BLKS) {
        int warp = blockIdx.x * 8 + (threadIdx.x >> 5);
        int lane = threadIdx.x & 31;
        float4 xv = *(const float4*)&x[(size_t)warp * Dd + lane * 4];
        __half2 h0 = __floats2half2_rn(xv.x, xv.y);
        __half2 h1 = __floats2half2_rn(xv.z, xv.w);
        uint2 packed;
        packed.x = *(uint32_t*)&h0;
        packed.y = *(uint32_t*)&h1;
        *(uint2*)&g_xh[(size_t)warp * Dd + lane * 4] = packed;
        float4 wq = *(const float4*)&g_wqa[lane * 4];
        float4 wk = *(const float4*)&g_wka[lane * 4];
        float a = xv.x * wq.x + xv.y * wq.y + xv.z * wq.z + xv.w * wq.w;
        float b = xv.x * wk.x + xv.y * wk.y + xv.z * wk.z + xv.w * wk.w;
        #pragma unroll
        for (int off = 16; off > 0; off >>= 1) {
            a += __shfl_xor_sync(0xffffffffu, a, off);
            b += __shfl_xor_sync(0xffffffffu, b, off);
        }
        if (lane == 0) g_qka[warp] = make_float2(a, b);
        return;
    }
    int q = (blockIdx.x - FX_BLKS) * 256 + threadIdx.x;   // quad index
    if (q >= Ee / 4) return;
    int4 s4 = ((const int4*)ei)[q];
    int4 b4 = ((const int4*)bi)[q];
    atomicAdd(&g_counts[b4.x * Nn + s4.x], 1);
    atomicAdd(&g_counts[b4.y * Nn + s4.y], 1);
    atomicAdd(&g_counts[b4.z * Nn + s4.z], 1);
    atomicAdd(&g_counts[b4.w * Nn + s4.w], 1);
}

// ---------------- K4: single-block exclusive scan of counts ------------------
#define SCAN_T 1024
#define SCAN_CH 40
__global__ void k_scan() {
    __shared__ int sh[SCAN_T];
    int t = threadIdx.x;
    int start = t * SCAN_CH;
    int end = min(start + SCAN_CH, NODES);
    int s = 0;
    for (int i = start; i < end; i++) s += g_counts[i];
    sh[t] = s;
    __syncthreads();
    for (int off = 1; off < SCAN_T; off <<= 1) {
        int v = (t >= off) ? sh[t - off] : 0;
        __syncthreads();
        sh[t] += v;
        __syncthreads();
    }
    int run = (t == 0) ? 0 : sh[t - 1];
    for (int i = start; i < end; i++) {
        g_offsets[i] = run;
        g_cursor[i] = run;
        run += g_counts[i];
    }
    if (t == SCAN_T - 1) g_offsets[NODES] = sh[SCAN_T - 1];
}

// ---------------- K5: edge pass — dot, exp, seg-sum, sorted record + fp16 row
__global__ __launch_bounds__(256) void k_edge1(const int* __restrict__ ei,
                                               const float* __restrict__ e_emb,
                                               const int* __restrict__ bi) {
    __shared__ float ws4[DE];
    __shared__ float s_cc;
    __shared__ float sdot[8][32];
    int t = threadIdx.x;
    if (t < DE) ws4[t] = g_wewa[t];
    if (t == 0) s_cc = g_cc;
    __syncthreads();

    int wid  = t >> 5;
    int lane = t & 31;
    int base = (blockIdx.x * 8 + wid) * 32;      // 32 edges per warp

    int e_mine = base + lane;
    int src = ei[e_mine];
    int dst = ei[Ee + e_mine];
    int b   = bi[e_mine];

    int oct  = lane >> 3;
    int sub  = lane & 7;
    float w0 = ws4[sub * 4 + 0], w1 = ws4[sub * 4 + 1];
    float w2 = ws4[sub * 4 + 2], w3 = ws4[sub * 4 + 3];
    #pragma unroll
    for (int g = 0; g < 8; g++) {
        int e4 = base + g * 4 + oct;
        float4 v = *(const float4*)&e_emb[(size_t)e4 * DE + sub * 4];
        float d = v.x * w0 + v.y * w1 + v.z * w2 + v.w * w3;
        d += __shfl_xor_sync(0xffffffffu, d, 4);
        d += __shfl_xor_sync(0xffffffffu, d, 2);
        d += __shfl_xor_sync(0xffffffffu, d, 1);
        if (sub == 0) sdot[wid][g * 4 + oct] = d;
    }
    __syncwarp();

    float dot = sdot[wid][lane];
    int key  = b * Nn + src;
    int dstn = b * Nn + dst;
    float2 qs = g_qka[key];
    float2 kd = g_qka[dstn];
    float logit = (qs.x + kd.y + dot + s_cc) * RSQRT_DH;
    float ex = __expf(logit);
    atomicAdd(&g_att_sum[dstn], ex);
    int pos = atomicAdd(&g_cursor[key], 1);
    g_edge2[pos] = make_int2(dstn, __float_as_int(ex));

    #pragma unroll
    for (int g = 0; g < 8; g++) {
        int j = g * 4 + oct;
        int pj = __shfl_sync(0xffffffffu, pos, j);
        int e4 = base + j;
        float4 v = *(const float4*)&e_emb[(size_t)e4 * DE + sub * 4];
        __half2 h0 = __floats2half2_rn(v.x, v.y);
        __half2 h1 = __floats2half2_rn(v.z, v.w);
        uint2 packed;
        packed.x = *(uint32_t*)&h0;
        packed.y = *(uint32_t*)&h1;
        *(uint2*)&g_eh[(size_t)pj * DE + sub * 4] = packed;
    }
}

// ---------------- K6: gather moments, one warp per src node (8-wide batch) ---
__global__ __launch_bounds__(128) void k_gather() {
    int s = blockIdx.x * 4 + (threadIdx.x >> 5);
    int lane = threadIdx.x & 31;
    if (s >= NODES) return;

    int start = g_offsets[s];
    int end   = g_offsets[s + 1];

    float4 accx = make_float4(0.f, 0.f, 0.f, 0.f);
    float acce = 0.f;
    float accA = 0.f;

    int i = start;
    for (; i + 8 <= end; i += 8) {
        int2 m[8];
        #pragma unroll
        for (int k = 0; k < 8; k++) m[k] = g_edge2[i + k];
        uint2 r[8];
        #pragma unroll
        for (int k = 0; k < 8; k++)
            r[k] = *(const uint2*)&g_xh[(size_t)m[k].x * Dd + lane * 4];
        float h[8];
        #pragma unroll
        for (int k = 0; k < 8; k++)
            h[k] = __half2float(g_eh[(size_t)(i + k) * DE + lane]);
        float sm[8];
        #pragma unroll
        for (int k = 0; k < 8; k++) sm[k] = g_att_sum[m[k].x];
        #pragma unroll
        for (int k = 0; k < 8; k++) {
            float a = __fdividef(__int_as_float(m[k].y), sm[k] + 1e-9f);
            float4 v = h4tof4(r[k]);
            accx.x += a * v.x; accx.y += a * v.y;
            accx.z += a * v.z; accx.w += a * v.w;
            acce += a * h[k];
            accA += a;
        }
    }
    for (; i < end; i++) {
        int2 m = g_edge2[i];
        float h = __half2float(g_eh[(size_t)i * DE + lane]);
        uint2 r = *(const uint2*)&g_xh[(size_t)m.x * Dd + lane * 4];
        float a = __fdividef(__int_as_float(m.y), g_att_sum[m.x] + 1e-9f);
        float4 v = h4tof4(r);
        accx.x += a * v.x; accx.y += a * v.y;
        accx.z += a * v.z; accx.w += a * v.w;
        acce += a * h;
        accA += a;
    }

    *(float4*)&g_Mx[(size_t)s * Dd + lane * 4] = accx;
    g_Me[(size_t)s * DE + lane] = acce;
    if (lane == 0) g_sA[s] = accA;
}

// ---------------- K7: tf32 tensor-core epilogue GEMM -------------------------
// out = [Mx|Me] @ [Wv;Wev] + sA ⊗ (bv+bev);  128x128 block tile, K=160.
#define OB_M 128
#define OB_K 16
#define NTILES 10
#define ASTR 20    // As row stride (floats): conflict-free A-fragment loads
#define BSTR 136   // Bs row stride (floats): conflict-free B-fragment loads
__global__ __launch_bounds__(256) void k_out(const float* __restrict__ Wv,
                                             const float* __restrict__ Wev,
                                             float* __restrict__ out) {
    __shared__ float As[2][OB_M * ASTR];
    __shared__ float Bs[2][OB_K * BSTR];
    __shared__ float sA_sh[OB_M];
    __shared__ float bb_sh[Dd];

    int t  = threadIdx.x;
    int m0 = blockIdx.x * OB_M;
    if (t < OB_M) {
        sA_sh[t] = g_sA[m0 + t];
        bb_sh[t] = g_bvev[t];
    }

    auto issue = [&](int stage, int tile) {
        #pragma unroll
        for (int it = 0; it < 2; it++) {
            int q = t + it * 256;
            int m = q >> 2, kq = q & 3;
            const float* srcA = (tile < 8)
                ? &g_Mx[(size_t)(m0 + m) * Dd + tile * OB_K + kq * 4]
                : &g_Me[(size_t)(m0 + m) * DE + (tile - 8) * OB_K + kq * 4];
            cp16(&As[stage][m * ASTR + kq * 4], srcA);
            int k = q >> 5, c4 = q & 31;
            const float* srcB = (tile < 8)
                ? &Wv[(size_t)(tile * OB_K + k) * Dd + c4 * 4]
                : &Wev[(size_t)((tile - 8) * OB_K + k) * Dd + c4 * 4];
            cp16(&Bs[stage][k * BSTR + c4 * 4], srcB);
        }
    };

    issue(0, 0);
    CP_COMMIT();

    int wid  = t >> 5;
    int lane = t & 31;
    int warp_m = wid >> 1;           // 0..3: 32-row slab
    int warp_n = wid & 1;            // 0..1: 64-col slab
    int gID = lane >> 2, tig = lane & 3;

    float d[2][8][4];
    #pragma unroll
    for (int mi = 0; mi < 2; mi++)
        #pragma unroll
        for (int ni = 0; ni < 8; ni++)
            #pragma unroll
            for (int k = 0; k < 4; k++) d[mi][ni][k] = 0.f;

    for (int tile = 0; tile < NTILES; tile++) {
        int cur = tile & 1, nxt = cur ^ 1;
        if (tile + 1 < NTILES) {
            issue(nxt, tile + 1);
            CP_COMMIT();
            CP_WAIT(1);
        } else {
            CP_WAIT(0);
        }
        __syncthreads();
        #pragma unroll
        for (int ks = 0; ks < OB_K; ks += 8) {
            uint32_t a[2][4];
            #pragma unroll
            for (int mi = 0; mi < 2; mi++) {
                int r0 = warp_m * 32 + mi * 16 + gID;
                a[mi][0] = f2tf32(As[cur][(r0)     * ASTR + ks + tig]);
                a[mi][1] = f2tf32(As[cur][(r0 + 8) * ASTR + ks + tig]);
                a[mi][2] = f2tf32(As[cur][(r0)     * ASTR + ks + tig + 4]);
                a[mi][3] = f2tf32(As[cur][(r0 + 8) * ASTR + ks + tig + 4]);
            }
            #pragma unroll
            for (int ni = 0; ni < 8; ni++) {
                int cn = warp_n * 64 + ni * 8 + gID;
                uint32_t b0 = f2tf32(Bs[cur][(ks + tig)     * BSTR + cn]);
                uint32_t b1 = f2tf32(Bs[cur][(ks + tig + 4) * BSTR + cn]);
                mma_tf32(d[0][ni], a[0], b0, b1);
                mma_tf32(d[1][ni], a[1], b0, b1);
            }
        }
        __syncthreads();
    }

    // Epilogue: D fragment c0,c1 at (row gID, cols 2*tig, 2*tig+1); c2,c3 at row gID+8
    #pragma unroll
    for (int mi = 0; mi < 2; mi++) {
        int rl = warp_m * 32 + mi * 16 + gID;   // local row (lo)
        int rh = rl + 8;
        int r_lo = m0 + rl, r_hi = m0 + rh;
        float sa_lo = sA_sh[rl], sa_hi = sA_sh[rh];
        #pragma unroll
        for (int ni = 0; ni < 8; ni++) {
            int c = warp_n * 64 + ni * 8 + tig * 2;
            float b0 = bb_sh[c], b1 = bb_sh[c + 1];
            if (r_lo < NODES) {
                float2 o = make_float2(d[mi][ni][0] + sa_lo * b0,
                                       d[mi][ni][1] + sa_lo * b1);
                *(float2*)&out[(size_t)r_lo * Dd + c] = o;
            }
            if (r_hi < NODES) {
                float2 o = make_float2(d[mi][ni][2] + sa_hi * b0,
                                       d[mi][ni][3] + sa_hi * b1);
                *(float2*)&out[(size_t)r_hi * Dd + c] = o;
            }
        }
    }
}

// ---------------- launch ------------------------------------------------------
extern "C" void kernel_launch(void* const* d_in, const int* in_sizes, int n_in,
                              void* d_out, int out_size) {
    const float* x     = (const float*)d_in[0];
    const int*   ei    = (const int*)  d_in[1];
    const float* e_emb = (const float*)d_in[2];
    const int*   bi    = (const int*)  d_in[3];
    const float* Wq    = (const float*)d_in[4];
    const float* bq    = (const float*)d_in[5];
    const float* Wk    = (const float*)d_in[6];
    const float* bk    = (const float*)d_in[7];
    const float* Wv    = (const float*)d_in[8];
    const float* bv    = (const float*)d_in[9];
    const float* Wew   = (const float*)d_in[10];
    const float* bew   = (const float*)d_in[11];
    const float* Wev   = (const float*)d_in[12];
    const float* bev   = (const float*)d_in[13];
    const float* Wa    = (const float*)d_in[14];
    float* out = (float*)d_out;

    k_init<<<ZERO_BLKS + 16, 256>>>(Wq, Wk, Wew, bq, bk, bew, Wa, bv, bev);
    k_fxc<<<FX_BLKS + (Ee / 4 + 255) / 256, 256>>>(x, ei, bi);
    k_scan<<<1, SCAN_T>>>();
    k_edge1<<<Ee / 256, 256>>>(ei, e_emb, bi);
    k_gather<<<(NODES + 3) / 4, 128>>>();
    k_out<<<NODES_PAD / OB_M, 256>>>(Wv, Wev, out);
}